// round 3
// baseline (speedup 1.0000x reference)
#include <cuda_runtime.h>

typedef unsigned long long u64t;

#define B_   8
#define C_   256
#define N_   4096
#define DQK  32

// Scratch (device globals — allocation-free rule)
__device__ float g_q[B_ * N_ * DQK];                 // [b][n][d]
__device__ float g_k[B_ * N_ * DQK];                 // [b][n][d]
__device__ float g_v[(size_t)B_ * N_ * C_];          // [b][n][c]

// ---------------- packed f32x2 helpers (Blackwell FFMA2 path) ----------------
__device__ __forceinline__ u64t f2_fma(u64t a, u64t b, u64t c) {
    u64t d;
    asm("fma.rn.f32x2 %0, %1, %2, %3;" : "=l"(d) : "l"(a), "l"(b), "l"(c));
    return d;
}
__device__ __forceinline__ u64t f2_mul(u64t a, u64t b) {
    u64t d;
    asm("mul.rn.f32x2 %0, %1, %2;" : "=l"(d) : "l"(a), "l"(b));
    return d;
}
__device__ __forceinline__ u64t f2_pack(float x, float y) {
    u64t d;
    asm("mov.b64 %0, {%1, %2};" : "=l"(d) : "f"(x), "f"(y));
    return d;
}
__device__ __forceinline__ float2 f2_unpack(u64t a) {
    float2 r;
    asm("mov.b64 {%0, %1}, %2;" : "=f"(r.x), "=f"(r.y) : "l"(a));
    return r;
}

// ---------------- projection kernel ----------------
// 4-row register-blocked dot: rows' weights loaded as float4 broadcasts (all
// lanes in a warp share the same row set), x from padded smem (conflict-free).
__device__ __forceinline__ void dot4(const float* __restrict__ xs, int n,
                                     const float* __restrict__ w0,
                                     const float* __restrict__ w1,
                                     const float* __restrict__ w2,
                                     const float* __restrict__ w3,
                                     float& a0, float& a1, float& a2, float& a3) {
#pragma unroll 8
    for (int c = 0; c < 256; c += 4) {
        float x0 = xs[(c + 0) * 33 + n];
        float x1 = xs[(c + 1) * 33 + n];
        float x2 = xs[(c + 2) * 33 + n];
        float x3 = xs[(c + 3) * 33 + n];
        float4 m;
        m = *(const float4*)(w0 + c); a0 += x0 * m.x + x1 * m.y + x2 * m.z + x3 * m.w;
        m = *(const float4*)(w1 + c); a1 += x0 * m.x + x1 * m.y + x2 * m.z + x3 * m.w;
        m = *(const float4*)(w2 + c); a2 += x0 * m.x + x1 * m.y + x2 * m.z + x3 * m.w;
        m = *(const float4*)(w3 + c); a3 += x0 * m.x + x1 * m.y + x2 * m.z + x3 * m.w;
    }
}

__global__ __launch_bounds__(256)
void proj_kernel(const float* __restrict__ x,
                 const float* __restrict__ wq, const float* __restrict__ bq,
                 const float* __restrict__ wk, const float* __restrict__ bk,
                 const float* __restrict__ wv, const float* __restrict__ bv) {
    __shared__ float xs[256 * 33];
    const int b  = blockIdx.y;
    const int n0 = blockIdx.x * 32;
    const int t  = threadIdx.x;

    const float* xb = x + (size_t)b * C_ * N_;
#pragma unroll
    for (int r = 0; r < 32; r++) {
        int idx = t + r * 256;
        int c = idx >> 5, n = idx & 31;
        xs[c * 33 + n] = xb[(size_t)c * N_ + n0 + n];
    }
    __syncthreads();

    const int n  = t & 31;     // pixel within tile (same for all this thread's outputs)
    const int dg = t >> 5;     // row group 0..7 (warp-uniform -> broadcast weight loads)
    const size_t nbase = (size_t)b * N_ + n0 + n;

    // Q
    {
        float a0 = bq[dg], a1 = bq[dg + 8], a2 = bq[dg + 16], a3 = bq[dg + 24];
        dot4(xs, n, wq + (size_t)dg * 256, wq + (size_t)(dg + 8) * 256,
                     wq + (size_t)(dg + 16) * 256, wq + (size_t)(dg + 24) * 256,
             a0, a1, a2, a3);
        float* qo = g_q + nbase * 32;
        qo[dg] = a0; qo[dg + 8] = a1; qo[dg + 16] = a2; qo[dg + 24] = a3;
    }
    // K
    {
        float a0 = bk[dg], a1 = bk[dg + 8], a2 = bk[dg + 16], a3 = bk[dg + 24];
        dot4(xs, n, wk + (size_t)dg * 256, wk + (size_t)(dg + 8) * 256,
                     wk + (size_t)(dg + 16) * 256, wk + (size_t)(dg + 24) * 256,
             a0, a1, a2, a3);
        float* ko = g_k + nbase * 32;
        ko[dg] = a0; ko[dg + 8] = a1; ko[dg + 16] = a2; ko[dg + 24] = a3;
    }
    // V (8 groups of 4 rows)
    float* vo = g_v + nbase * 256;
    for (int gg = 0; gg < 8; gg++) {
        int c0 = dg + 32 * gg;
        float a0 = bv[c0], a1 = bv[c0 + 8], a2 = bv[c0 + 16], a3 = bv[c0 + 24];
        dot4(xs, n, wv + (size_t)c0 * 256, wv + (size_t)(c0 + 8) * 256,
                     wv + (size_t)(c0 + 16) * 256, wv + (size_t)(c0 + 24) * 256,
             a0, a1, a2, a3);
        vo[c0] = a0; vo[c0 + 8] = a1; vo[c0 + 16] = a2; vo[c0 + 24] = a3;
    }
}

// ---------------- fused flash attention kernel ----------------
// CTA: (64 queries) x (one batch). Streams TJ=32 keys/values per tile.
// smem floats layout (dynamic, 65536 bytes total):
//   q_s   [64][34]   @ 0      (2176)
//   k_s   [32][32]   @ 2176   (1024)
//   p_s   [32][128]  @ 3200   (4096)  scores / duplicated probabilities
//   v_s   [32][256]  @ 7296   (8192)
//   pmax  [4][64]    @ 15488
//   psum  [4][64]    @ 15744
//   m_s   [64]       @ 16000
//   l_s   [64]       @ 16064
//   a_s   [64]       @ 16128
// epilogue reuses the whole 16384-float region as a [64][256] staging buffer.
__global__ __launch_bounds__(256, 2)
void attn_kernel(const float* __restrict__ x, const float* __restrict__ alphap,
                 float* __restrict__ out) {
    extern __shared__ float sm[];
    float* q_s  = sm;
    float* k_s  = sm + 2176;
    float* p_s  = sm + 3200;
    float* v_s  = sm + 7296;
    float* pmax = sm + 15488;
    float* psum = sm + 15744;
    float* m_s  = sm + 16000;
    float* l_s  = sm + 16064;
    float* a_s  = sm + 16128;

    const int b  = blockIdx.y;
    const int i0 = blockIdx.x * 64;
    const int t  = threadIdx.x;

    const float* qg = g_q + ((size_t)b * N_ + i0) * 32;
    const float* kg = g_k + (size_t)b * N_ * 32;
    const float* vg = g_v + (size_t)b * N_ * 256;

#pragma unroll
    for (int r = 0; r < 8; r++) {
        int idx = t + r * 256;
        int i = idx >> 5, d = idx & 31;
        q_s[i * 34 + d] = qg[i * 32 + d];
    }
    if (t < 64) { m_s[t] = -1e30f; l_s[t] = 0.f; }

    u64t acc[8][4];
#pragma unroll
    for (int ii = 0; ii < 8; ii++)
#pragma unroll
        for (int cc = 0; cc < 4; cc++) acc[ii][cc] = 0ull;
    __syncthreads();

    const int si = t & 63, sg = t >> 6;           // score/softmax mapping
    const int ti = t & 7,  tc = t >> 3;           // PV mapping
    const int c0 = tc * 8;

    for (int jt = 0; jt < 128; jt++) {
        const int j0 = jt * 32;
        // --- load k tile (1024 floats) and v tile (8192 floats), coalesced float4
        {
            int j = t >> 3, d4 = t & 7;
            *(float4*)&k_s[j * 32 + d4 * 4] =
                *(const float4*)&kg[(size_t)(j0 + j) * 32 + d4 * 4];
        }
#pragma unroll
        for (int r = 0; r < 8; r++) {
            int idx = t + r * 256;
            int j = idx >> 6, c4 = idx & 63;
            *(float4*)&v_s[j * 256 + c4 * 4] =
                *(const float4*)&vg[(size_t)(j0 + j) * 256 + c4 * 4];
        }
        __syncthreads();

        // --- scores: s[j][i] = q_i . k_j  (q in regs; k_s reads are warp-broadcast)
        {
            const u64t* qp = (const u64t*)&q_s[si * 34];
            u64t q2[16];
#pragma unroll
            for (int d2 = 0; d2 < 16; d2++) q2[d2] = qp[d2];
#pragma unroll
            for (int jj = 0; jj < 8; jj++) {
                int j = sg * 8 + jj;
                const u64t* kp = (const u64t*)&k_s[j * 32];
                u64t s2 = 0ull;
#pragma unroll
                for (int d2 = 0; d2 < 16; d2++) s2 = f2_fma(q2[d2], kp[d2], s2);
                float2 sv = f2_unpack(s2);
                p_s[j * 128 + 2 * si] = sv.x + sv.y;
            }
        }
        __syncthreads();

        // --- online softmax over this tile (column i, 4 threads per column)
        float lm = -1e30f;
#pragma unroll
        for (int jj = 0; jj < 8; jj++)
            lm = fmaxf(lm, p_s[(sg * 8 + jj) * 128 + 2 * si]);
        pmax[sg * 64 + si] = lm;
        __syncthreads();

        float mt = fmaxf(fmaxf(pmax[si], pmax[64 + si]),
                         fmaxf(pmax[128 + si], pmax[192 + si]));
        float mold = m_s[si];
        float mnew = fmaxf(mold, mt);
        float al   = __expf(mold - mnew);
        if (sg == 0) a_s[si] = al;

        float lsum = 0.f;
#pragma unroll
        for (int jj = 0; jj < 8; jj++) {
            int j = sg * 8 + jj;
            float p = __expf(p_s[j * 128 + 2 * si] - mnew);
            p_s[j * 128 + 2 * si]     = p;   // duplicated pair -> loadable {p,p}
            p_s[j * 128 + 2 * si + 1] = p;
            lsum += p;
        }
        psum[sg * 64 + si] = lsum;
        __syncthreads();

        if (sg == 0) {
            m_s[si] = mnew;
            l_s[si] = l_s[si] * al + psum[si] + psum[64 + si] + psum[128 + si] + psum[192 + si];
        }

        // --- rescale accumulators by this tile's alpha
#pragma unroll
        for (int ii = 0; ii < 8; ii++) {
            float a = a_s[ti * 8 + ii];
            u64t a2 = f2_pack(a, a);
#pragma unroll
            for (int cc = 0; cc < 4; cc++) acc[ii][cc] = f2_mul(acc[ii][cc], a2);
        }

        // --- PV: acc[i][c] += p[j][i] * v[j][c]   (8i x 8c per thread, f32x2)
#pragma unroll 2
        for (int j = 0; j < 32; j++) {
            const ulonglong2* pp = (const ulonglong2*)&p_s[j * 128 + ti * 16];
            ulonglong2 pA = pp[0], pB = pp[1], pC = pp[2], pD = pp[3];
            u64t pv[8] = {pA.x, pA.y, pB.x, pB.y, pC.x, pC.y, pD.x, pD.y};
            const ulonglong2* vp = (const ulonglong2*)&v_s[j * 256 + c0];
            ulonglong2 vA = vp[0], vB = vp[1];
            u64t vv[4] = {vA.x, vA.y, vB.x, vB.y};
#pragma unroll
            for (int ii = 0; ii < 8; ii++)
#pragma unroll
                for (int cc = 0; cc < 4; cc++)
                    acc[ii][cc] = f2_fma(pv[ii], vv[cc], acc[ii][cc]);
        }
        __syncthreads();
    }

    // ---------------- epilogue ----------------
    const float alpha0 = *alphap;
    const float invl   = alpha0 / l_s[t & 63];   // read BEFORE smem reuse
    __syncthreads();

    // stage acc -> sm as [64 i][256 c] with per-row column rotation (bank-safe read)
    float* stage = sm;
#pragma unroll
    for (int ii = 0; ii < 8; ii++) {
        int i = ti * 8 + ii;
#pragma unroll
        for (int cc = 0; cc < 4; cc++) {
            float2 v2 = f2_unpack(acc[ii][cc]);
            int cA = c0 + 2 * cc;
            stage[i * 256 + ((cA + i) & 255)]     = v2.x;
            stage[i * 256 + ((cA + 1 + i) & 255)] = v2.y;
        }
    }
    __syncthreads();

    {
        int i  = t & 63;
        int cg = t >> 6;
        size_t obase = (size_t)b * C_ * N_ + (size_t)(i0 + i);
#pragma unroll 4
        for (int r = 0; r < 64; r++) {
            int c = cg + 4 * r;
            size_t idx = obase + (size_t)c * N_;
            out[idx] = stage[i * 256 + ((c + i) & 255)] * invl + x[idx];
        }
    }
}

// ---------------- launch ----------------
extern "C" void kernel_launch(void* const* d_in, const int* in_sizes, int n_in,
                              void* d_out, int out_size) {
    const float* x     = (const float*)d_in[0];
    const float* wq    = (const float*)d_in[1];
    const float* bq    = (const float*)d_in[2];
    const float* wk    = (const float*)d_in[3];
    const float* bk    = (const float*)d_in[4];
    const float* wv    = (const float*)d_in[5];
    const float* bv    = (const float*)d_in[6];
    const float* alpha = (const float*)d_in[7];
    float* out = (float*)d_out;

    cudaFuncSetAttribute(attn_kernel, cudaFuncAttributeMaxDynamicSharedMemorySize, 65536);

    proj_kernel<<<dim3(N_ / 32, B_), 256>>>(x, wq, bq, wk, bk, wv, bv);
    attn_kernel<<<dim3(N_ / 64, B_), 256, 65536>>>(x, alpha, out);
}

// round 4
// speedup vs baseline: 1.0002x; 1.0002x over previous
#include <cuda_runtime.h>

typedef unsigned long long u64t;

#define B_   8
#define C_   256
#define N_   4096
#define DQK  32

// Scratch (device globals — allocation-free rule)
__device__ float g_q[B_ * N_ * DQK];                 // [b][n][d]
__device__ float g_k[B_ * N_ * DQK];                 // [b][n][d]
__device__ float g_v[(size_t)B_ * N_ * C_];          // [b][n][c]

// ---------------- packed f32x2 helpers (Blackwell FFMA2 path) ----------------
__device__ __forceinline__ u64t f2_fma(u64t a, u64t b, u64t c) {
    u64t d;
    asm("fma.rn.f32x2 %0, %1, %2, %3;" : "=l"(d) : "l"(a), "l"(b), "l"(c));
    return d;
}
__device__ __forceinline__ u64t f2_mul(u64t a, u64t b) {
    u64t d;
    asm("mul.rn.f32x2 %0, %1, %2;" : "=l"(d) : "l"(a), "l"(b));
    return d;
}
__device__ __forceinline__ u64t f2_pack(float x, float y) {
    u64t d;
    asm("mov.b64 %0, {%1, %2};" : "=l"(d) : "f"(x), "f"(y));
    return d;
}
__device__ __forceinline__ float2 f2_unpack(u64t a) {
    float2 r;
    asm("mov.b64 {%0, %1}, %2;" : "=f"(r.x), "=f"(r.y) : "l"(a));
    return r;
}

// ---------------- projection kernel ----------------
// 4-row register-blocked dot: rows' weights loaded as float4 broadcasts (all
// lanes in a warp share the same row set), x from padded smem (conflict-free).
__device__ __forceinline__ void dot4(const float* __restrict__ xs, int n,
                                     const float* __restrict__ w0,
                                     const float* __restrict__ w1,
                                     const float* __restrict__ w2,
                                     const float* __restrict__ w3,
                                     float& a0, float& a1, float& a2, float& a3) {
#pragma unroll 8
    for (int c = 0; c < 256; c += 4) {
        float x0 = xs[(c + 0) * 33 + n];
        float x1 = xs[(c + 1) * 33 + n];
        float x2 = xs[(c + 2) * 33 + n];
        float x3 = xs[(c + 3) * 33 + n];
        float4 m;
        m = *(const float4*)(w0 + c); a0 += x0 * m.x + x1 * m.y + x2 * m.z + x3 * m.w;
        m = *(const float4*)(w1 + c); a1 += x0 * m.x + x1 * m.y + x2 * m.z + x3 * m.w;
        m = *(const float4*)(w2 + c); a2 += x0 * m.x + x1 * m.y + x2 * m.z + x3 * m.w;
        m = *(const float4*)(w3 + c); a3 += x0 * m.x + x1 * m.y + x2 * m.z + x3 * m.w;
    }
}

__global__ __launch_bounds__(256)
void proj_kernel(const float* __restrict__ x,
                 const float* __restrict__ wq, const float* __restrict__ bq,
                 const float* __restrict__ wk, const float* __restrict__ bk,
                 const float* __restrict__ wv, const float* __restrict__ bv) {
    __shared__ float xs[256 * 33];
    const int b  = blockIdx.y;
    const int n0 = blockIdx.x * 32;
    const int t  = threadIdx.x;

    const float* xb = x + (size_t)b * C_ * N_;
#pragma unroll
    for (int r = 0; r < 32; r++) {
        int idx = t + r * 256;
        int c = idx >> 5, n = idx & 31;
        xs[c * 33 + n] = xb[(size_t)c * N_ + n0 + n];
    }
    __syncthreads();

    const int n  = t & 31;     // pixel within tile (same for all this thread's outputs)
    const int dg = t >> 5;     // row group 0..7 (warp-uniform -> broadcast weight loads)
    const size_t nbase = (size_t)b * N_ + n0 + n;

    // Q
    {
        float a0 = bq[dg], a1 = bq[dg + 8], a2 = bq[dg + 16], a3 = bq[dg + 24];
        dot4(xs, n, wq + (size_t)dg * 256, wq + (size_t)(dg + 8) * 256,
                     wq + (size_t)(dg + 16) * 256, wq + (size_t)(dg + 24) * 256,
             a0, a1, a2, a3);
        float* qo = g_q + nbase * 32;
        qo[dg] = a0; qo[dg + 8] = a1; qo[dg + 16] = a2; qo[dg + 24] = a3;
    }
    // K
    {
        float a0 = bk[dg], a1 = bk[dg + 8], a2 = bk[dg + 16], a3 = bk[dg + 24];
        dot4(xs, n, wk + (size_t)dg * 256, wk + (size_t)(dg + 8) * 256,
                     wk + (size_t)(dg + 16) * 256, wk + (size_t)(dg + 24) * 256,
             a0, a1, a2, a3);
        float* ko = g_k + nbase * 32;
        ko[dg] = a0; ko[dg + 8] = a1; ko[dg + 16] = a2; ko[dg + 24] = a3;
    }
    // V (8 groups of 4 rows)
    float* vo = g_v + nbase * 256;
    for (int gg = 0; gg < 8; gg++) {
        int c0 = dg + 32 * gg;
        float a0 = bv[c0], a1 = bv[c0 + 8], a2 = bv[c0 + 16], a3 = bv[c0 + 24];
        dot4(xs, n, wv + (size_t)c0 * 256, wv + (size_t)(c0 + 8) * 256,
                     wv + (size_t)(c0 + 16) * 256, wv + (size_t)(c0 + 24) * 256,
             a0, a1, a2, a3);
        vo[c0] = a0; vo[c0 + 8] = a1; vo[c0 + 16] = a2; vo[c0 + 24] = a3;
    }
}

// ---------------- fused flash attention kernel ----------------
// CTA: (64 queries) x (one batch). Streams TJ=32 keys/values per tile.
// smem floats layout (dynamic, 65536 bytes total):
//   q_s   [64][34]   @ 0      (2176)
//   k_s   [32][32]   @ 2176   (1024)
//   p_s   [32][128]  @ 3200   (4096)  scores / duplicated probabilities
//   v_s   [32][256]  @ 7296   (8192)
//   pmax  [4][64]    @ 15488
//   psum  [4][64]    @ 15744
//   m_s   [64]       @ 16000
//   l_s   [64]       @ 16064
//   a_s   [64]       @ 16128
// epilogue reuses the whole 16384-float region as a [64][256] staging buffer.
__global__ __launch_bounds__(256, 2)
void attn_kernel(const float* __restrict__ x, const float* __restrict__ alphap,
                 float* __restrict__ out) {
    extern __shared__ float sm[];
    float* q_s  = sm;
    float* k_s  = sm + 2176;
    float* p_s  = sm + 3200;
    float* v_s  = sm + 7296;
    float* pmax = sm + 15488;
    float* psum = sm + 15744;
    float* m_s  = sm + 16000;
    float* l_s  = sm + 16064;
    float* a_s  = sm + 16128;

    const int b  = blockIdx.y;
    const int i0 = blockIdx.x * 64;
    const int t  = threadIdx.x;

    const float* qg = g_q + ((size_t)b * N_ + i0) * 32;
    const float* kg = g_k + (size_t)b * N_ * 32;
    const float* vg = g_v + (size_t)b * N_ * 256;

#pragma unroll
    for (int r = 0; r < 8; r++) {
        int idx = t + r * 256;
        int i = idx >> 5, d = idx & 31;
        q_s[i * 34 + d] = qg[i * 32 + d];
    }
    if (t < 64) { m_s[t] = -1e30f; l_s[t] = 0.f; }

    u64t acc[8][4];
#pragma unroll
    for (int ii = 0; ii < 8; ii++)
#pragma unroll
        for (int cc = 0; cc < 4; cc++) acc[ii][cc] = 0ull;
    __syncthreads();

    const int si = t & 63, sg = t >> 6;           // score/softmax mapping
    const int ti = t & 7,  tc = t >> 3;           // PV mapping
    const int c0 = tc * 8;

    for (int jt = 0; jt < 128; jt++) {
        const int j0 = jt * 32;
        // --- load k tile (1024 floats) and v tile (8192 floats), coalesced float4
        {
            int j = t >> 3, d4 = t & 7;
            *(float4*)&k_s[j * 32 + d4 * 4] =
                *(const float4*)&kg[(size_t)(j0 + j) * 32 + d4 * 4];
        }
#pragma unroll
        for (int r = 0; r < 8; r++) {
            int idx = t + r * 256;
            int j = idx >> 6, c4 = idx & 63;
            *(float4*)&v_s[j * 256 + c4 * 4] =
                *(const float4*)&vg[(size_t)(j0 + j) * 256 + c4 * 4];
        }
        __syncthreads();

        // --- scores: s[j][i] = q_i . k_j  (q in regs; k_s reads are warp-broadcast)
        {
            const u64t* qp = (const u64t*)&q_s[si * 34];
            u64t q2[16];
#pragma unroll
            for (int d2 = 0; d2 < 16; d2++) q2[d2] = qp[d2];
#pragma unroll
            for (int jj = 0; jj < 8; jj++) {
                int j = sg * 8 + jj;
                const u64t* kp = (const u64t*)&k_s[j * 32];
                u64t s2 = 0ull;
#pragma unroll
                for (int d2 = 0; d2 < 16; d2++) s2 = f2_fma(q2[d2], kp[d2], s2);
                float2 sv = f2_unpack(s2);
                p_s[j * 128 + 2 * si] = sv.x + sv.y;
            }
        }
        __syncthreads();

        // --- online softmax over this tile (column i, 4 threads per column)
        float lm = -1e30f;
#pragma unroll
        for (int jj = 0; jj < 8; jj++)
            lm = fmaxf(lm, p_s[(sg * 8 + jj) * 128 + 2 * si]);
        pmax[sg * 64 + si] = lm;
        __syncthreads();

        float mt = fmaxf(fmaxf(pmax[si], pmax[64 + si]),
                         fmaxf(pmax[128 + si], pmax[192 + si]));
        float mold = m_s[si];
        float mnew = fmaxf(mold, mt);
        float al   = __expf(mold - mnew);
        if (sg == 0) a_s[si] = al;

        float lsum = 0.f;
#pragma unroll
        for (int jj = 0; jj < 8; jj++) {
            int j = sg * 8 + jj;
            float p = __expf(p_s[j * 128 + 2 * si] - mnew);
            p_s[j * 128 + 2 * si]     = p;   // duplicated pair -> loadable {p,p}
            p_s[j * 128 + 2 * si + 1] = p;
            lsum += p;
        }
        psum[sg * 64 + si] = lsum;
        __syncthreads();

        if (sg == 0) {
            m_s[si] = mnew;
            l_s[si] = l_s[si] * al + psum[si] + psum[64 + si] + psum[128 + si] + psum[192 + si];
        }

        // --- rescale accumulators by this tile's alpha
#pragma unroll
        for (int ii = 0; ii < 8; ii++) {
            float a = a_s[ti * 8 + ii];
            u64t a2 = f2_pack(a, a);
#pragma unroll
            for (int cc = 0; cc < 4; cc++) acc[ii][cc] = f2_mul(acc[ii][cc], a2);
        }

        // --- PV: acc[i][c] += p[j][i] * v[j][c]   (8i x 8c per thread, f32x2)
#pragma unroll 2
        for (int j = 0; j < 32; j++) {
            const ulonglong2* pp = (const ulonglong2*)&p_s[j * 128 + ti * 16];
            ulonglong2 pA = pp[0], pB = pp[1], pC = pp[2], pD = pp[3];
            u64t pv[8] = {pA.x, pA.y, pB.x, pB.y, pC.x, pC.y, pD.x, pD.y};
            const ulonglong2* vp = (const ulonglong2*)&v_s[j * 256 + c0];
            ulonglong2 vA = vp[0], vB = vp[1];
            u64t vv[4] = {vA.x, vA.y, vB.x, vB.y};
#pragma unroll
            for (int ii = 0; ii < 8; ii++)
#pragma unroll
                for (int cc = 0; cc < 4; cc++)
                    acc[ii][cc] = f2_fma(pv[ii], vv[cc], acc[ii][cc]);
        }
        __syncthreads();
    }

    // ---------------- epilogue ----------------
    const float alpha0 = *alphap;
    const float invl   = alpha0 / l_s[t & 63];   // read BEFORE smem reuse
    __syncthreads();

    // stage acc -> sm as [64 i][256 c] with per-row column rotation (bank-safe read)
    float* stage = sm;
#pragma unroll
    for (int ii = 0; ii < 8; ii++) {
        int i = ti * 8 + ii;
#pragma unroll
        for (int cc = 0; cc < 4; cc++) {
            float2 v2 = f2_unpack(acc[ii][cc]);
            int cA = c0 + 2 * cc;
            stage[i * 256 + ((cA + i) & 255)]     = v2.x;
            stage[i * 256 + ((cA + 1 + i) & 255)] = v2.y;
        }
    }
    __syncthreads();

    {
        int i  = t & 63;
        int cg = t >> 6;
        size_t obase = (size_t)b * C_ * N_ + (size_t)(i0 + i);
#pragma unroll 4
        for (int r = 0; r < 64; r++) {
            int c = cg + 4 * r;
            size_t idx = obase + (size_t)c * N_;
            out[idx] = stage[i * 256 + ((c + i) & 255)] * invl + x[idx];
        }
    }
}

// ---------------- launch ----------------
extern "C" void kernel_launch(void* const* d_in, const int* in_sizes, int n_in,
                              void* d_out, int out_size) {
    const float* x     = (const float*)d_in[0];
    const float* wq    = (const float*)d_in[1];
    const float* bq    = (const float*)d_in[2];
    const float* wk    = (const float*)d_in[3];
    const float* bk    = (const float*)d_in[4];
    const float* wv    = (const float*)d_in[5];
    const float* bv    = (const float*)d_in[6];
    const float* alpha = (const float*)d_in[7];
    float* out = (float*)d_out;

    cudaFuncSetAttribute(attn_kernel, cudaFuncAttributeMaxDynamicSharedMemorySize, 65536);

    proj_kernel<<<dim3(N_ / 32, B_), 256>>>(x, wq, bq, wk, bk, wv, bv);
    attn_kernel<<<dim3(N_ / 64, B_), 256, 65536>>>(x, alpha, out);
}

// round 7
// speedup vs baseline: 3.5332x; 3.5324x over previous
#include <cuda_runtime.h>
#include <cuda_bf16.h>
#include <cstdint>

#define B_ 8
#define C_ 256
#define N_ 4096

typedef unsigned int u32;

// ---------------- device scratch (allocation-free rule) ----------------
__device__ __align__(16) __nv_bfloat16 g_qh[B_ * N_ * 32];   // [b][n][d]
__device__ __align__(16) __nv_bfloat16 g_ql[B_ * N_ * 32];
__device__ __align__(16) __nv_bfloat16 g_kh[B_ * N_ * 32];
__device__ __align__(16) __nv_bfloat16 g_kl[B_ * N_ * 32];
__device__ __align__(16) __nv_bfloat16 g_vh[(size_t)B_ * C_ * N_];  // [b][c][n]
__device__ __align__(16) __nv_bfloat16 g_vl[(size_t)B_ * C_ * N_];

// ---------------- helpers ----------------
__device__ __forceinline__ u32 smem_u32(const void* p) {
    u32 a;
    asm("{ .reg .u64 t; cvta.to.shared.u64 t, %1; cvt.u32.u64 %0, t; }" : "=r"(a) : "l"(p));
    return a;
}
__device__ __forceinline__ u32 pack_bf2(__nv_bfloat16 a, __nv_bfloat16 b) {
    __nv_bfloat162 t = __halves2bfloat162(a, b);
    return *reinterpret_cast<u32*>(&t);
}
__device__ __forceinline__ void mma_bf16(float* c, const u32* a, const u32* b) {
    asm volatile(
        "mma.sync.aligned.m16n8k16.row.col.f32.bf16.bf16.f32 "
        "{%0,%1,%2,%3}, {%4,%5,%6,%7}, {%8,%9}, {%0,%1,%2,%3};"
        : "+f"(c[0]), "+f"(c[1]), "+f"(c[2]), "+f"(c[3])
        : "r"(a[0]), "r"(a[1]), "r"(a[2]), "r"(a[3]), "r"(b[0]), "r"(b[1]));
}
__device__ __forceinline__ void ldm4(u32* r, u32 addr) {
    asm volatile("ldmatrix.sync.aligned.m8n8.x4.shared.b16 {%0,%1,%2,%3}, [%4];"
                 : "=r"(r[0]), "=r"(r[1]), "=r"(r[2]), "=r"(r[3]) : "r"(addr));
}
// ldmatrix address: 16-row region at (row0, colh halves), 40-half row stride
__device__ __forceinline__ u32 lma(u32 sb, u32 region, int row0, int colh, int lane) {
    int lr = lane & 15, lc = (lane >> 4) * 8;
    return sb + region + (u32)((row0 + lr) * 40 + colh + lc) * 2;
}

// smem byte offsets (all rows padded to 40 halves / 36 floats)
#define O_QH 0u
#define O_QL 5120u
#define O_KH 10240u
#define O_KL 12800u
#define O_VH 15360u
#define O_VL 35840u
#define O_S  56320u
#define O_PH 65536u
#define O_PL 70656u
#define O_M  75776u
#define O_L  76032u
#define O_A  76288u
#define SMEM_BYTES 76544u

// ---------------- projection kernel ----------------
__device__ __forceinline__ void dot4(const float* __restrict__ xs, int n,
                                     const float* __restrict__ w0, const float* __restrict__ w1,
                                     const float* __restrict__ w2, const float* __restrict__ w3,
                                     float& a0, float& a1, float& a2, float& a3) {
#pragma unroll 8
    for (int c = 0; c < 256; c += 4) {
        float x0 = xs[(c + 0) * 33 + n], x1 = xs[(c + 1) * 33 + n];
        float x2 = xs[(c + 2) * 33 + n], x3 = xs[(c + 3) * 33 + n];
        float4 m;
        m = *(const float4*)(w0 + c); a0 += x0 * m.x + x1 * m.y + x2 * m.z + x3 * m.w;
        m = *(const float4*)(w1 + c); a1 += x0 * m.x + x1 * m.y + x2 * m.z + x3 * m.w;
        m = *(const float4*)(w2 + c); a2 += x0 * m.x + x1 * m.y + x2 * m.z + x3 * m.w;
        m = *(const float4*)(w3 + c); a3 += x0 * m.x + x1 * m.y + x2 * m.z + x3 * m.w;
    }
}

__device__ __forceinline__ void split_store(__nv_bfloat16* hi, __nv_bfloat16* lo,
                                            float a0, float a1, float a2, float a3) {
    __nv_bfloat16 h0 = __float2bfloat16(a0), h1 = __float2bfloat16(a1);
    __nv_bfloat16 h2 = __float2bfloat16(a2), h3 = __float2bfloat16(a3);
    uint2 hv; hv.x = pack_bf2(h0, h1); hv.y = pack_bf2(h2, h3);
    uint2 lv;
    lv.x = pack_bf2(__float2bfloat16(a0 - __bfloat162float(h0)),
                    __float2bfloat16(a1 - __bfloat162float(h1)));
    lv.y = pack_bf2(__float2bfloat16(a2 - __bfloat162float(h2)),
                    __float2bfloat16(a3 - __bfloat162float(h3)));
    *(uint2*)hi = hv; *(uint2*)lo = lv;
}

__global__ __launch_bounds__(256)
void proj_kernel(const float* __restrict__ x,
                 const float* __restrict__ wq, const float* __restrict__ bq,
                 const float* __restrict__ wk, const float* __restrict__ bk,
                 const float* __restrict__ wv, const float* __restrict__ bv) {
    __shared__ float xs[256 * 33];
    const int b = blockIdx.y, n0 = blockIdx.x * 32, t = threadIdx.x;
    const float* xb = x + (size_t)b * C_ * N_;
#pragma unroll
    for (int r = 0; r < 32; r++) {
        int idx = t + r * 256, c = idx >> 5, n = idx & 31;
        xs[c * 33 + n] = xb[(size_t)c * N_ + n0 + n];
    }
    __syncthreads();
    const int n = t & 31, dg = t >> 5, r0 = dg * 4;
    const size_t nbase = (size_t)b * N_ + n0 + n;
    {   // Q
        float a0 = bq[r0], a1 = bq[r0 + 1], a2 = bq[r0 + 2], a3 = bq[r0 + 3];
        dot4(xs, n, wq + (size_t)r0 * 256, wq + (size_t)(r0 + 1) * 256,
             wq + (size_t)(r0 + 2) * 256, wq + (size_t)(r0 + 3) * 256, a0, a1, a2, a3);
        split_store(&g_qh[nbase * 32 + r0], &g_ql[nbase * 32 + r0], a0, a1, a2, a3);
    }
    {   // K
        float a0 = bk[r0], a1 = bk[r0 + 1], a2 = bk[r0 + 2], a3 = bk[r0 + 3];
        dot4(xs, n, wk + (size_t)r0 * 256, wk + (size_t)(r0 + 1) * 256,
             wk + (size_t)(r0 + 2) * 256, wk + (size_t)(r0 + 3) * 256, a0, a1, a2, a3);
        split_store(&g_kh[nbase * 32 + r0], &g_kl[nbase * 32 + r0], a0, a1, a2, a3);
    }
    // V: write transposed + split directly to [b][c][n]
#pragma unroll
    for (int gg = 0; gg < 8; gg++) {
        int c0 = gg * 32 + r0;
        float a0 = bv[c0], a1 = bv[c0 + 1], a2 = bv[c0 + 2], a3 = bv[c0 + 3];
        dot4(xs, n, wv + (size_t)c0 * 256, wv + (size_t)(c0 + 1) * 256,
             wv + (size_t)(c0 + 2) * 256, wv + (size_t)(c0 + 3) * 256, a0, a1, a2, a3);
        float av[4] = {a0, a1, a2, a3};
#pragma unroll
        for (int e = 0; e < 4; e++) {
            size_t o = ((size_t)(b * C_ + c0 + e) << 12) + n0 + n;
            __nv_bfloat16 h = __float2bfloat16(av[e]);
            g_vh[o] = h;
            g_vl[o] = __float2bfloat16(av[e] - __bfloat162float(h));
        }
    }
}

// ---------------- flash attention via mma.sync (HMMA) ----------------
// CTA: 64 queries (i) x one batch; j-tiles of 32; O held transposed [c][i] in frags.
__global__ __launch_bounds__(256, 2)
void attn_kernel(const float* __restrict__ x, const float* __restrict__ alphap,
                 float* __restrict__ out) {
    extern __shared__ char smem[];
    const u32 sb = smem_u32(smem);
    float* m_s = (float*)(smem + O_M);
    float* l_s = (float*)(smem + O_L);
    float* a_s = (float*)(smem + O_A);

    const int b = blockIdx.y, i0 = blockIdx.x * 64;
    const int t = threadIdx.x, wid = t >> 5, lane = t & 31;

    // stage q hi/lo into smem (64 rows x 32 halves -> 40-padded)
    {
        int row = t >> 2, cq = t & 3;
        size_t g = ((size_t)(b * N_ + i0 + row) << 5) + cq * 8;
        *(uint4*)(smem + O_QH + row * 80 + cq * 16) = *(const uint4*)(g_qh + g);
        *(uint4*)(smem + O_QL + row * 80 + cq * 16) = *(const uint4*)(g_ql + g);
    }
    if (t < 64) { m_s[t] = -1e30f; l_s[t] = 0.f; }

    float acc[4][4][4];
#pragma unroll
    for (int m = 0; m < 4; m++)
#pragma unroll
        for (int nb = 0; nb < 4; nb++)
#pragma unroll
            for (int k = 0; k < 4; k++) acc[m][nb][k] = 0.f;
    __syncthreads();

    const int swI = (wid & 3) * 16, swJ = (wid >> 2) * 16;   // S-mma warp tile
    const int cO = (wid & 3) * 64, iO = (wid >> 2) * 32;     // PV warp tile

    for (int jt = 0; jt < 128; jt++) {
        const int j0 = jt * 32;
        // ---- load k tile (hi: t<128, lo: t>=128) and v tiles ----
        {
            int tt = t & 127, row = tt >> 2, cq = tt & 3;
            size_t g = ((size_t)(b * N_ + j0 + row) << 5) + cq * 8;
            const __nv_bfloat16* src = (t < 128) ? g_kh : g_kl;
            u32 dreg = (t < 128) ? O_KH : O_KL;
            *(uint4*)(smem + dreg + row * 80 + cq * 16) = *(const uint4*)(src + g);
        }
#pragma unroll
        for (int rr = 0; rr < 4; rr++) {
            int row = rr * 64 + (t >> 2), cq = t & 3;
            size_t g = ((size_t)(b * C_ + row) << 12) + j0 + cq * 8;
            *(uint4*)(smem + O_VH + row * 80 + cq * 16) = *(const uint4*)(g_vh + g);
            *(uint4*)(smem + O_VL + row * 80 + cq * 16) = *(const uint4*)(g_vl + g);
        }
        __syncthreads();

        // ---- S = Q.K^T (16i x 16j per warp), bf16 3-pass split ----
        {
            float sc[2][4];
#pragma unroll
            for (int nb = 0; nb < 2; nb++)
#pragma unroll
                for (int k = 0; k < 4; k++) sc[nb][k] = 0.f;
            u32 AH[2][4], AL[2][4], BH[2][2][2], BL[2][2][2];
#pragma unroll
            for (int kb = 0; kb < 2; kb++) {
                ldm4(AH[kb], lma(sb, O_QH, swI, kb * 16, lane));
                ldm4(AL[kb], lma(sb, O_QL, swI, kb * 16, lane));
                u32 r[4];
                ldm4(r, lma(sb, O_KH, swJ, kb * 16, lane));
                BH[kb][0][0] = r[0]; BH[kb][1][0] = r[1]; BH[kb][0][1] = r[2]; BH[kb][1][1] = r[3];
                ldm4(r, lma(sb, O_KL, swJ, kb * 16, lane));
                BL[kb][0][0] = r[0]; BL[kb][1][0] = r[1]; BL[kb][0][1] = r[2]; BL[kb][1][1] = r[3];
            }
#pragma unroll
            for (int kb = 0; kb < 2; kb++)
#pragma unroll
                for (int nb = 0; nb < 2; nb++) {
                    mma_bf16(sc[nb], AH[kb], BH[kb][nb]);
                    mma_bf16(sc[nb], AL[kb], BH[kb][nb]);
                    mma_bf16(sc[nb], AH[kb], BL[kb][nb]);
                }
            // write S[i][j] (36-float row stride)
#pragma unroll
            for (int nb = 0; nb < 2; nb++) {
                int r0 = swI + (lane >> 2), c0 = swJ + nb * 8 + (lane & 3) * 2;
                *(float2*)(smem + O_S + (u32)(r0 * 36 + c0) * 4) =
                    make_float2(sc[nb][0], sc[nb][1]);
                *(float2*)(smem + O_S + (u32)((r0 + 8) * 36 + c0) * 4) =
                    make_float2(sc[nb][2], sc[nb][3]);
            }
        }
        __syncthreads();

        // ---- online softmax: row i = t>>2, 8 j per thread ----
        {
            int irow = t >> 2, qj = t & 3;
            const float* sp = (const float*)(smem + O_S + (u32)(irow * 36 + qj * 8) * 4);
            float4 sA = *(const float4*)sp;
            float4 sB = *(const float4*)(sp + 4);
            float tm = fmaxf(fmaxf(fmaxf(sA.x, sA.y), fmaxf(sA.z, sA.w)),
                             fmaxf(fmaxf(sB.x, sB.y), fmaxf(sB.z, sB.w)));
            tm = fmaxf(tm, __shfl_xor_sync(0xffffffffu, tm, 1));
            tm = fmaxf(tm, __shfl_xor_sync(0xffffffffu, tm, 2));
            float mold = m_s[irow];
            float mnew = fmaxf(mold, tm);
            float alpha = __expf(mold - mnew);
            float p[8];
            p[0] = __expf(sA.x - mnew); p[1] = __expf(sA.y - mnew);
            p[2] = __expf(sA.z - mnew); p[3] = __expf(sA.w - mnew);
            p[4] = __expf(sB.x - mnew); p[5] = __expf(sB.y - mnew);
            p[6] = __expf(sB.z - mnew); p[7] = __expf(sB.w - mnew);
            float ls = 0.f;
#pragma unroll
            for (int k = 0; k < 8; k++) ls += p[k];
            ls += __shfl_xor_sync(0xffffffffu, ls, 1);
            ls += __shfl_xor_sync(0xffffffffu, ls, 2);
            uint4 hw, lw;
            u32* hp = (u32*)&hw; u32* lp = (u32*)&lw;
#pragma unroll
            for (int k = 0; k < 4; k++) {
                __nv_bfloat16 h0 = __float2bfloat16(p[2 * k]);
                __nv_bfloat16 h1 = __float2bfloat16(p[2 * k + 1]);
                hp[k] = pack_bf2(h0, h1);
                lp[k] = pack_bf2(__float2bfloat16(p[2 * k] - __bfloat162float(h0)),
                                 __float2bfloat16(p[2 * k + 1] - __bfloat162float(h1)));
            }
            *(uint4*)(smem + O_PH + irow * 80 + qj * 16) = hw;
            *(uint4*)(smem + O_PL + irow * 80 + qj * 16) = lw;
            if (qj == 0) {
                m_s[irow] = mnew;
                a_s[irow] = alpha;
                l_s[irow] = l_s[irow] * alpha + ls;
            }
        }
        __syncthreads();

        // ---- rescale O accum, then PV mma (A=V [c][j], B=P [i][j]) ----
#pragma unroll
        for (int nb = 0; nb < 4; nb++) {
            int irow = iO + nb * 8 + (lane & 3) * 2;
            float a0 = a_s[irow], a1 = a_s[irow + 1];
#pragma unroll
            for (int m = 0; m < 4; m++) {
                acc[m][nb][0] *= a0; acc[m][nb][1] *= a1;
                acc[m][nb][2] *= a0; acc[m][nb][3] *= a1;
            }
        }
#pragma unroll
        for (int g = 0; g < 2; g++) {
            u32 BH[2][2][2], BL[2][2][2];
#pragma unroll
            for (int kb = 0; kb < 2; kb++) {
                u32 r[4];
                ldm4(r, lma(sb, O_PH, iO + g * 16, kb * 16, lane));
                BH[kb][0][0] = r[0]; BH[kb][1][0] = r[1]; BH[kb][0][1] = r[2]; BH[kb][1][1] = r[3];
                ldm4(r, lma(sb, O_PL, iO + g * 16, kb * 16, lane));
                BL[kb][0][0] = r[0]; BL[kb][1][0] = r[1]; BL[kb][0][1] = r[2]; BL[kb][1][1] = r[3];
            }
#pragma unroll
            for (int m = 0; m < 4; m++) {
                u32 AH[2][4], AL[2][4];
                ldm4(AH[0], lma(sb, O_VH, cO + m * 16, 0, lane));
                ldm4(AH[1], lma(sb, O_VH, cO + m * 16, 16, lane));
                ldm4(AL[0], lma(sb, O_VL, cO + m * 16, 0, lane));
                ldm4(AL[1], lma(sb, O_VL, cO + m * 16, 16, lane));
#pragma unroll
                for (int nbl = 0; nbl < 2; nbl++) {
                    int nb = g * 2 + nbl;
#pragma unroll
                    for (int kb = 0; kb < 2; kb++) {
                        mma_bf16(acc[m][nb], AH[kb], BH[kb][nbl]);
                        mma_bf16(acc[m][nb], AL[kb], BH[kb][nbl]);
                        mma_bf16(acc[m][nb], AH[kb], BL[kb][nbl]);
                    }
                }
            }
        }
        __syncthreads();
    }

    // ---- epilogue: out[b][c][i0+i] = alpha0 * O[c][i] / l[i] + x ----
    const float alpha0 = alphap[0];
#pragma unroll
    for (int nb = 0; nb < 4; nb++) {
        int irow = iO + nb * 8 + (lane & 3) * 2;
        float s0 = alpha0 / l_s[irow], s1 = alpha0 / l_s[irow + 1];
#pragma unroll
        for (int m = 0; m < 4; m++) {
            int c = cO + m * 16 + (lane >> 2);
            size_t g0 = ((size_t)(b * C_ + c) << 12) + i0 + irow;
            float2 x0 = *(const float2*)(x + g0);
            float2 o0;
            o0.x = acc[m][nb][0] * s0 + x0.x;
            o0.y = acc[m][nb][1] * s1 + x0.y;
            *(float2*)(out + g0) = o0;
            size_t g1 = g0 + ((size_t)8 << 12);
            float2 x1 = *(const float2*)(x + g1);
            float2 o1;
            o1.x = acc[m][nb][2] * s0 + x1.x;
            o1.y = acc[m][nb][3] * s1 + x1.y;
            *(float2*)(out + g1) = o1;
        }
    }
}

// ---------------- launch ----------------
extern "C" void kernel_launch(void* const* d_in, const int* in_sizes, int n_in,
                              void* d_out, int out_size) {
    const float* x     = (const float*)d_in[0];
    const float* wq    = (const float*)d_in[1];
    const float* bq    = (const float*)d_in[2];
    const float* wk    = (const float*)d_in[3];
    const float* bk    = (const float*)d_in[4];
    const float* wv    = (const float*)d_in[5];
    const float* bv    = (const float*)d_in[6];
    const float* alpha = (const float*)d_in[7];
    float* out = (float*)d_out;

    cudaFuncSetAttribute(attn_kernel, cudaFuncAttributeMaxDynamicSharedMemorySize, SMEM_BYTES);

    proj_kernel<<<dim3(N_ / 32, B_), 256>>>(x, wq, bq, wk, bk, wv, bv);
    attn_kernel<<<dim3(N_ / 64, B_), 256, SMEM_BYTES>>>(x, alpha, out);
}

// round 8
// speedup vs baseline: 3.5548x; 1.0061x over previous
#include <cuda_runtime.h>
#include <cuda_bf16.h>
#include <cstdint>

#define B_ 8
#define C_ 256
#define N_ 4096

typedef unsigned int u32;

// ---------------- device scratch (allocation-free rule) ----------------
__device__ __align__(16) __nv_bfloat16 g_qh[B_ * N_ * 32];   // [b][n][d]
__device__ __align__(16) __nv_bfloat16 g_ql[B_ * N_ * 32];
__device__ __align__(16) __nv_bfloat16 g_kh[B_ * N_ * 32];
__device__ __align__(16) __nv_bfloat16 g_kl[B_ * N_ * 32];
__device__ __align__(16) __nv_bfloat16 g_vh[(size_t)B_ * C_ * N_];  // [b][c][n]
__device__ __align__(16) __nv_bfloat16 g_vl[(size_t)B_ * C_ * N_];

// ---------------- helpers ----------------
__device__ __forceinline__ u32 smem_u32(const void* p) {
    u32 a;
    asm("{ .reg .u64 t; cvta.to.shared.u64 t, %1; cvt.u32.u64 %0, t; }" : "=r"(a) : "l"(p));
    return a;
}
__device__ __forceinline__ u32 pack_bf2(__nv_bfloat16 a, __nv_bfloat16 b) {
    __nv_bfloat162 t = __halves2bfloat162(a, b);
    return *reinterpret_cast<u32*>(&t);
}
__device__ __forceinline__ void mma_bf16(float* c, const u32* a, const u32* b) {
    asm volatile(
        "mma.sync.aligned.m16n8k16.row.col.f32.bf16.bf16.f32 "
        "{%0,%1,%2,%3}, {%4,%5,%6,%7}, {%8,%9}, {%0,%1,%2,%3};"
        : "+f"(c[0]), "+f"(c[1]), "+f"(c[2]), "+f"(c[3])
        : "r"(a[0]), "r"(a[1]), "r"(a[2]), "r"(a[3]), "r"(b[0]), "r"(b[1]));
}
__device__ __forceinline__ void ldm4(u32* r, u32 addr) {
    asm volatile("ldmatrix.sync.aligned.m8n8.x4.shared.b16 {%0,%1,%2,%3}, [%4];"
                 : "=r"(r[0]), "=r"(r[1]), "=r"(r[2]), "=r"(r[3]) : "r"(addr));
}
// ldmatrix address: 16-row region at (row0, colh halves), 40-half row stride
__device__ __forceinline__ u32 lma(u32 sb, u32 region, int row0, int colh, int lane) {
    int lr = lane & 15, lc = (lane >> 4) * 8;
    return sb + region + (u32)((row0 + lr) * 40 + colh + lc) * 2;
}
// split float pair -> hi bf16x2 and lo (residual) bf16x2
__device__ __forceinline__ void pack_split(float a, float b, u32& h, u32& l) {
    __nv_bfloat16 ha = __float2bfloat16(a), hb = __float2bfloat16(b);
    h = pack_bf2(ha, hb);
    l = pack_bf2(__float2bfloat16(a - __bfloat162float(ha)),
                 __float2bfloat16(b - __bfloat162float(hb)));
}

// smem byte offsets — K tiles [32 j][40 d-pad], V tiles [256 c][40 j-pad]
#define O_KH 0u
#define O_KL 2560u
#define O_VH 5120u
#define O_VL 25600u
#define O_STG 5120u           // epilogue f32 stage [128 c][68 i-pad]
#define SMEM_BYTES 46080u

// ---------------- projection kernel (unchanged, passing) ----------------
__device__ __forceinline__ void dot4(const float* __restrict__ xs, int n,
                                     const float* __restrict__ w0, const float* __restrict__ w1,
                                     const float* __restrict__ w2, const float* __restrict__ w3,
                                     float& a0, float& a1, float& a2, float& a3) {
#pragma unroll 8
    for (int c = 0; c < 256; c += 4) {
        float x0 = xs[(c + 0) * 33 + n], x1 = xs[(c + 1) * 33 + n];
        float x2 = xs[(c + 2) * 33 + n], x3 = xs[(c + 3) * 33 + n];
        float4 m;
        m = *(const float4*)(w0 + c); a0 += x0 * m.x + x1 * m.y + x2 * m.z + x3 * m.w;
        m = *(const float4*)(w1 + c); a1 += x0 * m.x + x1 * m.y + x2 * m.z + x3 * m.w;
        m = *(const float4*)(w2 + c); a2 += x0 * m.x + x1 * m.y + x2 * m.z + x3 * m.w;
        m = *(const float4*)(w3 + c); a3 += x0 * m.x + x1 * m.y + x2 * m.z + x3 * m.w;
    }
}

__device__ __forceinline__ void split_store(__nv_bfloat16* hi, __nv_bfloat16* lo,
                                            float a0, float a1, float a2, float a3) {
    u32 h0, l0, h1, l1;
    pack_split(a0, a1, h0, l0);
    pack_split(a2, a3, h1, l1);
    uint2 hv; hv.x = h0; hv.y = h1;
    uint2 lv; lv.x = l0; lv.y = l1;
    *(uint2*)hi = hv; *(uint2*)lo = lv;
}

__global__ __launch_bounds__(256)
void proj_kernel(const float* __restrict__ x,
                 const float* __restrict__ wq, const float* __restrict__ bq,
                 const float* __restrict__ wk, const float* __restrict__ bk,
                 const float* __restrict__ wv, const float* __restrict__ bv) {
    __shared__ float xs[256 * 33];
    const int b = blockIdx.y, n0 = blockIdx.x * 32, t = threadIdx.x;
    const float* xb = x + (size_t)b * C_ * N_;
#pragma unroll
    for (int r = 0; r < 32; r++) {
        int idx = t + r * 256, c = idx >> 5, n = idx & 31;
        xs[c * 33 + n] = xb[(size_t)c * N_ + n0 + n];
    }
    __syncthreads();
    const int n = t & 31, dg = t >> 5, r0 = dg * 4;
    const size_t nbase = (size_t)b * N_ + n0 + n;
    {   // Q
        float a0 = bq[r0], a1 = bq[r0 + 1], a2 = bq[r0 + 2], a3 = bq[r0 + 3];
        dot4(xs, n, wq + (size_t)r0 * 256, wq + (size_t)(r0 + 1) * 256,
             wq + (size_t)(r0 + 2) * 256, wq + (size_t)(r0 + 3) * 256, a0, a1, a2, a3);
        split_store(&g_qh[nbase * 32 + r0], &g_ql[nbase * 32 + r0], a0, a1, a2, a3);
    }
    {   // K
        float a0 = bk[r0], a1 = bk[r0 + 1], a2 = bk[r0 + 2], a3 = bk[r0 + 3];
        dot4(xs, n, wk + (size_t)r0 * 256, wk + (size_t)(r0 + 1) * 256,
             wk + (size_t)(r0 + 2) * 256, wk + (size_t)(r0 + 3) * 256, a0, a1, a2, a3);
        split_store(&g_kh[nbase * 32 + r0], &g_kl[nbase * 32 + r0], a0, a1, a2, a3);
    }
    // V: write transposed + split directly to [b][c][n]
#pragma unroll
    for (int gg = 0; gg < 8; gg++) {
        int c0 = gg * 32 + r0;
        float a0 = bv[c0], a1 = bv[c0 + 1], a2 = bv[c0 + 2], a3 = bv[c0 + 3];
        dot4(xs, n, wv + (size_t)c0 * 256, wv + (size_t)(c0 + 1) * 256,
             wv + (size_t)(c0 + 2) * 256, wv + (size_t)(c0 + 3) * 256, a0, a1, a2, a3);
        float av[4] = {a0, a1, a2, a3};
#pragma unroll
        for (int e = 0; e < 4; e++) {
            size_t o = ((size_t)(b * C_ + c0 + e) << 12) + n0 + n;
            __nv_bfloat16 h = __float2bfloat16(av[e]);
            g_vh[o] = h;
            g_vl[o] = __float2bfloat16(av[e] - __bfloat162float(h));
        }
    }
}

// ---------------- FA2-style flash attention, register-resident P ----------------
// CTA: 64 queries; 8 warps: warp group wg=wid>>1 owns rows wg*16..+15,
// (wid&1) selects c half (128 channels). j-tiles of 32. S/P never in smem.
__global__ __launch_bounds__(256, 2)
void attn_kernel(const float* __restrict__ x, const float* __restrict__ alphap,
                 float* __restrict__ out) {
    extern __shared__ char smem[];
    const u32 sb = smem_u32(smem);
    const int b = blockIdx.y, i0 = blockIdx.x * 64;
    const int t = threadIdx.x, wid = t >> 5, lane = t & 31;
    const int wg = wid >> 1, r0 = wg * 16;
    const int cw = (wid & 1) * 128;
    const int r = lane >> 2;

    // ---- stage Q (once), load A fragments, free the smem ----
    {
        int row = t >> 2, ck = t & 3;
        size_t g = ((size_t)(b * N_ + i0 + row) << 5) + ck * 8;
        *(uint4*)(smem + O_VH + row * 80 + ck * 16) = *(const uint4*)(g_qh + g);
        *(uint4*)(smem + O_VL + row * 80 + ck * 16) = *(const uint4*)(g_ql + g);
    }
    __syncthreads();
    u32 qh[2][4], ql[2][4];
    ldm4(qh[0], lma(sb, O_VH, r0, 0, lane));
    ldm4(qh[1], lma(sb, O_VH, r0, 16, lane));
    ldm4(ql[0], lma(sb, O_VL, r0, 0, lane));
    ldm4(ql[1], lma(sb, O_VL, r0, 16, lane));
    __syncthreads();

    float acc[16][4];
#pragma unroll
    for (int nb = 0; nb < 16; nb++)
#pragma unroll
        for (int e = 0; e < 4; e++) acc[nb][e] = 0.f;
    float m0 = -1e30f, m1 = -1e30f, l0 = 0.f, l1 = 0.f;

    const int krow = (t & 127) >> 2, kck = t & 3;
    const __nv_bfloat16* ksrc = (t < 128) ? g_kh : g_kl;
    const u32 kdst = (t < 128) ? O_KH : O_KL;
    const int vr = t >> 2, vck = t & 3;

    for (int jt = 0; jt < 128; jt++) {
        const int j0 = jt * 32;
        // ---- prefetch K/V tile into regs, then store after barrier ----
        uint4 kreg = *(const uint4*)(ksrc + ((size_t)(b * N_ + j0 + krow) << 5) + kck * 8);
        uint4 vhr[4], vlr[4];
#pragma unroll
        for (int rr = 0; rr < 4; rr++) {
            size_t g = ((size_t)(b * C_ + rr * 64 + vr) << 12) + j0 + vck * 8;
            vhr[rr] = *(const uint4*)(g_vh + g);
            vlr[rr] = *(const uint4*)(g_vl + g);
        }
        __syncthreads();
        *(uint4*)(smem + kdst + krow * 80 + kck * 16) = kreg;
#pragma unroll
        for (int rr = 0; rr < 4; rr++) {
            *(uint4*)(smem + O_VH + (rr * 64 + vr) * 80 + vck * 16) = vhr[rr];
            *(uint4*)(smem + O_VL + (rr * 64 + vr) * 80 + vck * 16) = vlr[rr];
        }
        __syncthreads();

        // ---- S = Q.K^T : 16 rows x 32 j per warp, 3-term bf16 split ----
        float sc[4][4];
#pragma unroll
        for (int nb = 0; nb < 4; nb++)
#pragma unroll
            for (int e = 0; e < 4; e++) sc[nb][e] = 0.f;
#pragma unroll
        for (int kb = 0; kb < 2; kb++)
#pragma unroll
            for (int jh = 0; jh < 2; jh++) {
                u32 rh[4], rl[4];
                ldm4(rh, lma(sb, O_KH, jh * 16, kb * 16, lane));
                ldm4(rl, lma(sb, O_KL, jh * 16, kb * 16, lane));
                u32 b0[2] = {rh[0], rh[2]}, b1[2] = {rh[1], rh[3]};
                u32 d0[2] = {rl[0], rl[2]}, d1[2] = {rl[1], rl[3]};
                mma_bf16(sc[jh * 2], qh[kb], b0);
                mma_bf16(sc[jh * 2], ql[kb], b0);
                mma_bf16(sc[jh * 2], qh[kb], d0);
                mma_bf16(sc[jh * 2 + 1], qh[kb], b1);
                mma_bf16(sc[jh * 2 + 1], ql[kb], b1);
                mma_bf16(sc[jh * 2 + 1], qh[kb], d1);
            }

        // ---- in-register online softmax (rows r and r+8) ----
        float mr0 = -1e30f, mr1 = -1e30f;
#pragma unroll
        for (int nb = 0; nb < 4; nb++) {
            mr0 = fmaxf(mr0, fmaxf(sc[nb][0], sc[nb][1]));
            mr1 = fmaxf(mr1, fmaxf(sc[nb][2], sc[nb][3]));
        }
        mr0 = fmaxf(mr0, __shfl_xor_sync(0xffffffffu, mr0, 1));
        mr0 = fmaxf(mr0, __shfl_xor_sync(0xffffffffu, mr0, 2));
        mr1 = fmaxf(mr1, __shfl_xor_sync(0xffffffffu, mr1, 1));
        mr1 = fmaxf(mr1, __shfl_xor_sync(0xffffffffu, mr1, 2));
        float mn0 = fmaxf(m0, mr0), mn1 = fmaxf(m1, mr1);
        float al0 = __expf(m0 - mn0), al1 = __expf(m1 - mn1);
        m0 = mn0; m1 = mn1;
        float p[4][4];
        float ls0 = 0.f, ls1 = 0.f;
#pragma unroll
        for (int nb = 0; nb < 4; nb++) {
            p[nb][0] = __expf(sc[nb][0] - mn0);
            p[nb][1] = __expf(sc[nb][1] - mn0);
            p[nb][2] = __expf(sc[nb][2] - mn1);
            p[nb][3] = __expf(sc[nb][3] - mn1);
            ls0 += p[nb][0] + p[nb][1];
            ls1 += p[nb][2] + p[nb][3];
        }
        ls0 += __shfl_xor_sync(0xffffffffu, ls0, 1);
        ls0 += __shfl_xor_sync(0xffffffffu, ls0, 2);
        ls1 += __shfl_xor_sync(0xffffffffu, ls1, 1);
        ls1 += __shfl_xor_sync(0xffffffffu, ls1, 2);
        l0 = l0 * al0 + ls0;
        l1 = l1 * al1 + ls1;
        // rescale output accumulators
#pragma unroll
        for (int nb = 0; nb < 16; nb++) {
            acc[nb][0] *= al0; acc[nb][1] *= al0;
            acc[nb][2] *= al1; acc[nb][3] *= al1;
        }
        // P -> A fragments (hi + residual lo), pure register conversion
        u32 ph[2][4], plo[2][4];
#pragma unroll
        for (int kb = 0; kb < 2; kb++) {
            pack_split(p[2 * kb][0], p[2 * kb][1], ph[kb][0], plo[kb][0]);
            pack_split(p[2 * kb][2], p[2 * kb][3], ph[kb][1], plo[kb][1]);
            pack_split(p[2 * kb + 1][0], p[2 * kb + 1][1], ph[kb][2], plo[kb][2]);
            pack_split(p[2 * kb + 1][2], p[2 * kb + 1][3], ph[kb][3], plo[kb][3]);
        }

        // ---- O += P.V : A=P (regs), B=V [c][j] (smem) ----
#pragma unroll
        for (int cb = 0; cb < 8; cb++) {
            int crow = cw + cb * 16;
            u32 vh0[4], vh1[4], vl0[4], vl1[4];
            ldm4(vh0, lma(sb, O_VH, crow, 0, lane));
            ldm4(vh1, lma(sb, O_VH, crow, 16, lane));
            ldm4(vl0, lma(sb, O_VL, crow, 0, lane));
            ldm4(vl1, lma(sb, O_VL, crow, 16, lane));
            u32 bh00[2] = {vh0[0], vh0[2]}, bh01[2] = {vh1[0], vh1[2]};
            u32 bh10[2] = {vh0[1], vh0[3]}, bh11[2] = {vh1[1], vh1[3]};
            u32 bl00[2] = {vl0[0], vl0[2]}, bl01[2] = {vl1[0], vl1[2]};
            u32 bl10[2] = {vl0[1], vl0[3]}, bl11[2] = {vl1[1], vl1[3]};
            float* A0 = acc[cb * 2];
            float* A1 = acc[cb * 2 + 1];
            mma_bf16(A0, ph[0], bh00); mma_bf16(A0, plo[0], bh00); mma_bf16(A0, ph[0], bl00);
            mma_bf16(A0, ph[1], bh01); mma_bf16(A0, plo[1], bh01); mma_bf16(A0, ph[1], bl01);
            mma_bf16(A1, ph[0], bh10); mma_bf16(A1, plo[0], bh10); mma_bf16(A1, ph[0], bl10);
            mma_bf16(A1, ph[1], bh11); mma_bf16(A1, plo[1], bh11); mma_bf16(A1, ph[1], bl11);
        }
    }
    __syncthreads();

    // ---- epilogue: stage O through smem, coalesced [b][c][n] writes ----
    const float alpha0 = alphap[0];
    const float s0 = alpha0 / l0, s1 = alpha0 / l1;
    float* stg = (float*)(smem + O_STG);
    const int qd = lane & 3;
#pragma unroll 1
    for (int phs = 0; phs < 2; phs++) {
        if ((wid & 1) == phs) {
#pragma unroll
            for (int nb = 0; nb < 16; nb++) {
                int c2 = nb * 8 + 2 * qd;
                int ir = r0 + r;
                stg[c2 * 68 + ir]           = acc[nb][0] * s0;
                stg[(c2 + 1) * 68 + ir]     = acc[nb][1] * s0;
                stg[c2 * 68 + ir + 8]       = acc[nb][2] * s1;
                stg[(c2 + 1) * 68 + ir + 8] = acc[nb][3] * s1;
            }
        }
        __syncthreads();
        int cbase = phs * 128;
#pragma unroll
        for (int pass = 0; pass < 2; pass++) {
            int c = pass * 64 + (t >> 2);
            int i4 = (t & 3) * 16;
            size_t g = ((size_t)(b * C_ + cbase + c) << 12) + i0 + i4;
#pragma unroll
            for (int e = 0; e < 4; e++) {
                float4 xr = *(const float4*)(x + g + e * 4);
                float4 vv = *(const float4*)&stg[c * 68 + i4 + e * 4];
                vv.x += xr.x; vv.y += xr.y; vv.z += xr.z; vv.w += xr.w;
                *(float4*)(out + g + e * 4) = vv;
            }
        }
        __syncthreads();
    }
}

// ---------------- launch ----------------
extern "C" void kernel_launch(void* const* d_in, const int* in_sizes, int n_in,
                              void* d_out, int out_size) {
    const float* x     = (const float*)d_in[0];
    const float* wq    = (const float*)d_in[1];
    const float* bq    = (const float*)d_in[2];
    const float* wk    = (const float*)d_in[3];
    const float* bk    = (const float*)d_in[4];
    const float* wv    = (const float*)d_in[5];
    const float* bv    = (const float*)d_in[6];
    const float* alpha = (const float*)d_in[7];
    float* out = (float*)d_out;

    cudaFuncSetAttribute(attn_kernel, cudaFuncAttributeMaxDynamicSharedMemorySize, SMEM_BYTES);

    proj_kernel<<<dim3(N_ / 32, B_), 256>>>(x, wq, bq, wk, bk, wv, bv);
    attn_kernel<<<dim3(N_ / 64, B_), 256, SMEM_BYTES>>>(x, alpha, out);
}

// round 10
// speedup vs baseline: 4.7506x; 1.3364x over previous
#include <cuda_runtime.h>
#include <cuda_bf16.h>
#include <cuda_fp16.h>
#include <cstdint>

#define B_ 8
#define C_ 256
#define N_ 4096

typedef unsigned int u32;

// ---------------- device scratch (allocation-free rule) ----------------
__device__ __align__(16) __nv_bfloat16 g_qh[B_ * N_ * 32];   // [b][n][d]
__device__ __align__(16) __nv_bfloat16 g_ql[B_ * N_ * 32];
__device__ __align__(16) __nv_bfloat16 g_kh[B_ * N_ * 32];
__device__ __align__(16) __nv_bfloat16 g_kl[B_ * N_ * 32];
__device__ __align__(16) __half       g_v16[(size_t)B_ * C_ * N_];  // [b][c][n] fp16

// ---------------- helpers ----------------
__device__ __forceinline__ u32 smem_u32(const void* p) {
    u32 a;
    asm("{ .reg .u64 t; cvta.to.shared.u64 t, %1; cvt.u32.u64 %0, t; }" : "=r"(a) : "l"(p));
    return a;
}
__device__ __forceinline__ u32 pack_bf2(__nv_bfloat16 a, __nv_bfloat16 b) {
    __nv_bfloat162 t = __halves2bfloat162(a, b);
    return *reinterpret_cast<u32*>(&t);
}
__device__ __forceinline__ void mma_bf16(float* c, const u32* a, const u32* b) {
    asm volatile(
        "mma.sync.aligned.m16n8k16.row.col.f32.bf16.bf16.f32 "
        "{%0,%1,%2,%3}, {%4,%5,%6,%7}, {%8,%9}, {%0,%1,%2,%3};"
        : "+f"(c[0]), "+f"(c[1]), "+f"(c[2]), "+f"(c[3])
        : "r"(a[0]), "r"(a[1]), "r"(a[2]), "r"(a[3]), "r"(b[0]), "r"(b[1]));
}
__device__ __forceinline__ void mma_f16(float* c, const u32* a, const u32* b) {
    asm volatile(
        "mma.sync.aligned.m16n8k16.row.col.f32.f16.f16.f32 "
        "{%0,%1,%2,%3}, {%4,%5,%6,%7}, {%8,%9}, {%0,%1,%2,%3};"
        : "+f"(c[0]), "+f"(c[1]), "+f"(c[2]), "+f"(c[3])
        : "r"(a[0]), "r"(a[1]), "r"(a[2]), "r"(a[3]), "r"(b[0]), "r"(b[1]));
}
__device__ __forceinline__ void ldm4(u32* r, u32 addr) {
    asm volatile("ldmatrix.sync.aligned.m8n8.x4.shared.b16 {%0,%1,%2,%3}, [%4];"
                 : "=r"(r[0]), "=r"(r[1]), "=r"(r[2]), "=r"(r[3]) : "r"(addr));
}
// ldmatrix address: 16-row region at (row0, colh halves), 40-half row stride
__device__ __forceinline__ u32 lma(u32 sb, u32 region, int row0, int colh, int lane) {
    int lr = lane & 15, lc = (lane >> 4) * 8;
    return sb + region + (u32)((row0 + lr) * 40 + colh + lc) * 2;
}
// bf16 split (for q/k)
__device__ __forceinline__ void pack_split(float a, float b, u32& h, u32& l) {
    __nv_bfloat16 ha = __float2bfloat16(a), hb = __float2bfloat16(b);
    h = pack_bf2(ha, hb);
    l = pack_bf2(__float2bfloat16(a - __bfloat162float(ha)),
                 __float2bfloat16(b - __bfloat162float(hb)));
}
// fp16 split (for P)
__device__ __forceinline__ void pack_split_h(float a, float b, u32& h, u32& l) {
    __half ha = __float2half_rn(a), hb = __float2half_rn(b);
    __half2 hh = __halves2half2(ha, hb);
    h = *reinterpret_cast<u32*>(&hh);
    __half2 ll = __halves2half2(__float2half_rn(a - __half2float(ha)),
                                __float2half_rn(b - __half2float(hb)));
    l = *reinterpret_cast<u32*>(&ll);
}

// smem byte offsets — K tiles [32 j][40 d-pad] bf16, V tile [256 c][40 j-pad] fp16
#define O_KH 0u
#define O_KL 2560u
#define O_V  5120u
#define O_STG 5120u           // epilogue f32 stage [128 c][68 i-pad] (reuses V)
#define SMEM_BYTES 39936u

// ---------------- projection kernel ----------------
__device__ __forceinline__ void dot4(const float* __restrict__ xs, int n,
                                     const float* __restrict__ w0, const float* __restrict__ w1,
                                     const float* __restrict__ w2, const float* __restrict__ w3,
                                     float& a0, float& a1, float& a2, float& a3) {
#pragma unroll 8
    for (int c = 0; c < 256; c += 4) {
        float x0 = xs[(c + 0) * 33 + n], x1 = xs[(c + 1) * 33 + n];
        float x2 = xs[(c + 2) * 33 + n], x3 = xs[(c + 3) * 33 + n];
        float4 m;
        m = *(const float4*)(w0 + c); a0 += x0 * m.x + x1 * m.y + x2 * m.z + x3 * m.w;
        m = *(const float4*)(w1 + c); a1 += x0 * m.x + x1 * m.y + x2 * m.z + x3 * m.w;
        m = *(const float4*)(w2 + c); a2 += x0 * m.x + x1 * m.y + x2 * m.z + x3 * m.w;
        m = *(const float4*)(w3 + c); a3 += x0 * m.x + x1 * m.y + x2 * m.z + x3 * m.w;
    }
}

__device__ __forceinline__ void split_store(__nv_bfloat16* hi, __nv_bfloat16* lo,
                                            float a0, float a1, float a2, float a3) {
    u32 h0, l0, h1, l1;
    pack_split(a0, a1, h0, l0);
    pack_split(a2, a3, h1, l1);
    uint2 hv; hv.x = h0; hv.y = h1;
    uint2 lv; lv.x = l0; lv.y = l1;
    *(uint2*)hi = hv; *(uint2*)lo = lv;
}

__global__ __launch_bounds__(256)
void proj_kernel(const float* __restrict__ x,
                 const float* __restrict__ wq, const float* __restrict__ bq,
                 const float* __restrict__ wk, const float* __restrict__ bk,
                 const float* __restrict__ wv, const float* __restrict__ bv) {
    __shared__ float xs[256 * 33];
    const int b = blockIdx.y, n0 = blockIdx.x * 32, t = threadIdx.x;
    const float* xb = x + (size_t)b * C_ * N_;
#pragma unroll
    for (int r = 0; r < 32; r++) {
        int idx = t + r * 256, c = idx >> 5, n = idx & 31;
        xs[c * 33 + n] = xb[(size_t)c * N_ + n0 + n];
    }
    __syncthreads();
    const int n = t & 31, dg = t >> 5, r0 = dg * 4;
    const size_t nbase = (size_t)b * N_ + n0 + n;
    {   // Q
        float a0 = bq[r0], a1 = bq[r0 + 1], a2 = bq[r0 + 2], a3 = bq[r0 + 3];
        dot4(xs, n, wq + (size_t)r0 * 256, wq + (size_t)(r0 + 1) * 256,
             wq + (size_t)(r0 + 2) * 256, wq + (size_t)(r0 + 3) * 256, a0, a1, a2, a3);
        split_store(&g_qh[nbase * 32 + r0], &g_ql[nbase * 32 + r0], a0, a1, a2, a3);
    }
    {   // K
        float a0 = bk[r0], a1 = bk[r0 + 1], a2 = bk[r0 + 2], a3 = bk[r0 + 3];
        dot4(xs, n, wk + (size_t)r0 * 256, wk + (size_t)(r0 + 1) * 256,
             wk + (size_t)(r0 + 2) * 256, wk + (size_t)(r0 + 3) * 256, a0, a1, a2, a3);
        split_store(&g_kh[nbase * 32 + r0], &g_kl[nbase * 32 + r0], a0, a1, a2, a3);
    }
    // V: fp16 transposed [b][c][n]
#pragma unroll
    for (int gg = 0; gg < 8; gg++) {
        int c0 = gg * 32 + r0;
        float a0 = bv[c0], a1 = bv[c0 + 1], a2 = bv[c0 + 2], a3 = bv[c0 + 3];
        dot4(xs, n, wv + (size_t)c0 * 256, wv + (size_t)(c0 + 1) * 256,
             wv + (size_t)(c0 + 2) * 256, wv + (size_t)(c0 + 3) * 256, a0, a1, a2, a3);
        float av[4] = {a0, a1, a2, a3};
#pragma unroll
        for (int e = 0; e < 4; e++) {
            size_t o = ((size_t)(b * C_ + c0 + e) << 12) + n0 + n;
            g_v16[o] = __float2half_rn(av[e]);
        }
    }
}

// ---------------- FA2-style flash attention ----------------
// CTA: 64 queries; warp group wg=wid>>1 owns rows wg*16..+15, (wid&1) = c half.
// QK: bf16 3-term split. PV: P fp16 hi+lo (regs) x V fp16 (2 terms).
__global__ __launch_bounds__(256, 2)
void attn_kernel(const float* __restrict__ x, const float* __restrict__ alphap,
                 float* __restrict__ out) {
    extern __shared__ char smem[];
    const u32 sb = smem_u32(smem);
    const int b = blockIdx.y, i0 = blockIdx.x * 64;
    const int t = threadIdx.x, wid = t >> 5, lane = t & 31;
    const int wg = wid >> 1, r0 = wg * 16;
    const int cw = (wid & 1) * 128;
    const int r = lane >> 2;

    // ---- stage Q (once), load A fragments, free the smem ----
    {
        int row = t >> 2, ck = t & 3;
        size_t g = ((size_t)(b * N_ + i0 + row) << 5) + ck * 8;
        *(uint4*)(smem + O_V + row * 80 + ck * 16) = *(const uint4*)(g_qh + g);
        *(uint4*)(smem + O_V + 10240 + row * 80 + ck * 16) = *(const uint4*)(g_ql + g);
    }
    __syncthreads();
    u32 qh[2][4], ql[2][4];
    ldm4(qh[0], lma(sb, O_V, r0, 0, lane));
    ldm4(qh[1], lma(sb, O_V, r0, 16, lane));
    ldm4(ql[0], lma(sb, O_V + 10240, r0, 0, lane));
    ldm4(ql[1], lma(sb, O_V + 10240, r0, 16, lane));
    __syncthreads();

    float acc[16][4];
#pragma unroll
    for (int nb = 0; nb < 16; nb++)
#pragma unroll
        for (int e = 0; e < 4; e++) acc[nb][e] = 0.f;
    float m0 = -1e30f, m1 = -1e30f, l0 = 0.f, l1 = 0.f;

    const int krow = (t & 127) >> 2, kck = t & 3;
    const __nv_bfloat16* ksrc = (t < 128) ? g_kh : g_kl;
    const u32 kdst = (t < 128) ? O_KH : O_KL;
    const int vr = t >> 2, vck = t & 3;

    for (int jt = 0; jt < 128; jt++) {
        const int j0 = jt * 32;
        // ---- prefetch K/V tile into regs, then store after barrier ----
        uint4 kreg = *(const uint4*)(ksrc + ((size_t)(b * N_ + j0 + krow) << 5) + kck * 8);
        uint4 vhr[4];
#pragma unroll
        for (int rr = 0; rr < 4; rr++) {
            size_t g = ((size_t)(b * C_ + rr * 64 + vr) << 12) + j0 + vck * 8;
            vhr[rr] = *(const uint4*)(g_v16 + g);
        }
        __syncthreads();
        *(uint4*)(smem + kdst + krow * 80 + kck * 16) = kreg;
#pragma unroll
        for (int rr = 0; rr < 4; rr++)
            *(uint4*)(smem + O_V + (rr * 64 + vr) * 80 + vck * 16) = vhr[rr];
        __syncthreads();

        // ---- S = Q.K^T : 16 rows x 32 j per warp, 3-term bf16 split ----
        float sc[4][4];
#pragma unroll
        for (int nb = 0; nb < 4; nb++)
#pragma unroll
            for (int e = 0; e < 4; e++) sc[nb][e] = 0.f;
#pragma unroll
        for (int kb = 0; kb < 2; kb++)
#pragma unroll
            for (int jh = 0; jh < 2; jh++) {
                u32 rh[4], rl[4];
                ldm4(rh, lma(sb, O_KH, jh * 16, kb * 16, lane));
                ldm4(rl, lma(sb, O_KL, jh * 16, kb * 16, lane));
                u32 b0[2] = {rh[0], rh[2]}, b1[2] = {rh[1], rh[3]};
                u32 d0[2] = {rl[0], rl[2]}, d1[2] = {rl[1], rl[3]};
                mma_bf16(sc[jh * 2], qh[kb], b0);
                mma_bf16(sc[jh * 2], ql[kb], b0);
                mma_bf16(sc[jh * 2], qh[kb], d0);
                mma_bf16(sc[jh * 2 + 1], qh[kb], b1);
                mma_bf16(sc[jh * 2 + 1], ql[kb], b1);
                mma_bf16(sc[jh * 2 + 1], qh[kb], d1);
            }

        // ---- in-register online softmax (rows r and r+8) ----
        float mr0 = -1e30f, mr1 = -1e30f;
#pragma unroll
        for (int nb = 0; nb < 4; nb++) {
            mr0 = fmaxf(mr0, fmaxf(sc[nb][0], sc[nb][1]));
            mr1 = fmaxf(mr1, fmaxf(sc[nb][2], sc[nb][3]));
        }
        mr0 = fmaxf(mr0, __shfl_xor_sync(0xffffffffu, mr0, 1));
        mr0 = fmaxf(mr0, __shfl_xor_sync(0xffffffffu, mr0, 2));
        mr1 = fmaxf(mr1, __shfl_xor_sync(0xffffffffu, mr1, 1));
        mr1 = fmaxf(mr1, __shfl_xor_sync(0xffffffffu, mr1, 2));
        float mn0 = fmaxf(m0, mr0), mn1 = fmaxf(m1, mr1);
        float al0 = __expf(m0 - mn0), al1 = __expf(m1 - mn1);
        m0 = mn0; m1 = mn1;
        float p[4][4];
        float ls0 = 0.f, ls1 = 0.f;
#pragma unroll
        for (int nb = 0; nb < 4; nb++) {
            p[nb][0] = __expf(sc[nb][0] - mn0);
            p[nb][1] = __expf(sc[nb][1] - mn0);
            p[nb][2] = __expf(sc[nb][2] - mn1);
            p[nb][3] = __expf(sc[nb][3] - mn1);
            ls0 += p[nb][0] + p[nb][1];
            ls1 += p[nb][2] + p[nb][3];
        }
        ls0 += __shfl_xor_sync(0xffffffffu, ls0, 1);
        ls0 += __shfl_xor_sync(0xffffffffu, ls0, 2);
        ls1 += __shfl_xor_sync(0xffffffffu, ls1, 1);
        ls1 += __shfl_xor_sync(0xffffffffu, ls1, 2);
        l0 = l0 * al0 + ls0;
        l1 = l1 * al1 + ls1;
        // rescale output accumulators
#pragma unroll
        for (int nb = 0; nb < 16; nb++) {
            acc[nb][0] *= al0; acc[nb][1] *= al0;
            acc[nb][2] *= al1; acc[nb][3] *= al1;
        }
        // P -> fp16 A fragments (hi + residual lo), pure register conversion
        u32 ph[2][4], plo[2][4];
#pragma unroll
        for (int kb = 0; kb < 2; kb++) {
            pack_split_h(p[2 * kb][0], p[2 * kb][1], ph[kb][0], plo[kb][0]);
            pack_split_h(p[2 * kb][2], p[2 * kb][3], ph[kb][1], plo[kb][1]);
            pack_split_h(p[2 * kb + 1][0], p[2 * kb + 1][1], ph[kb][2], plo[kb][2]);
            pack_split_h(p[2 * kb + 1][2], p[2 * kb + 1][3], ph[kb][3], plo[kb][3]);
        }

        // ---- O += P.V : A=P (regs, fp16), B=V fp16 [c][j] (smem), 2 terms ----
#pragma unroll
        for (int cb = 0; cb < 8; cb++) {
            int crow = cw + cb * 16;
            u32 v0[4], v1[4];
            ldm4(v0, lma(sb, O_V, crow, 0, lane));
            ldm4(v1, lma(sb, O_V, crow, 16, lane));
            u32 b00[2] = {v0[0], v0[2]}, b01[2] = {v1[0], v1[2]};
            u32 b10[2] = {v0[1], v0[3]}, b11[2] = {v1[1], v1[3]};
            float* A0 = acc[cb * 2];
            float* A1 = acc[cb * 2 + 1];
            mma_f16(A0, ph[0], b00); mma_f16(A0, plo[0], b00);
            mma_f16(A0, ph[1], b01); mma_f16(A0, plo[1], b01);
            mma_f16(A1, ph[0], b10); mma_f16(A1, plo[0], b10);
            mma_f16(A1, ph[1], b11); mma_f16(A1, plo[1], b11);
        }
    }
    __syncthreads();

    // ---- epilogue: stage O through smem, coalesced [b][c][n] writes ----
    const float alpha0 = alphap[0];
    const float s0 = alpha0 / l0, s1 = alpha0 / l1;
    float* stg = (float*)(smem + O_STG);
    const int qd = lane & 3;
#pragma unroll 1
    for (int phs = 0; phs < 2; phs++) {
        if ((wid & 1) == phs) {
#pragma unroll
            for (int nb = 0; nb < 16; nb++) {
                int c2 = nb * 8 + 2 * qd;
                int ir = r0 + r;
                stg[c2 * 68 + ir]           = acc[nb][0] * s0;
                stg[(c2 + 1) * 68 + ir]     = acc[nb][1] * s0;
                stg[c2 * 68 + ir + 8]       = acc[nb][2] * s1;
                stg[(c2 + 1) * 68 + ir + 8] = acc[nb][3] * s1;
            }
        }
        __syncthreads();
        int cbase = phs * 128;
#pragma unroll
        for (int pass = 0; pass < 2; pass++) {
            int c = pass * 64 + (t >> 2);
            int i4 = (t & 3) * 16;
            size_t g = ((size_t)(b * C_ + cbase + c) << 12) + i0 + i4;
#pragma unroll
            for (int e = 0; e < 4; e++) {
                float4 xr = *(const float4*)(x + g + e * 4);
                float4 vv = *(const float4*)&stg[c * 68 + i4 + e * 4];
                vv.x += xr.x; vv.y += xr.y; vv.z += xr.z; vv.w += xr.w;
                *(float4*)(out + g + e * 4) = vv;
            }
        }
        __syncthreads();
    }
}

// ---------------- launch ----------------
extern "C" void kernel_launch(void* const* d_in, const int* in_sizes, int n_in,
                              void* d_out, int out_size) {
    const float* x     = (const float*)d_in[0];
    const float* wq    = (const float*)d_in[1];
    const float* bq    = (const float*)d_in[2];
    const float* wk    = (const float*)d_in[3];
    const float* bk    = (const float*)d_in[4];
    const float* wv    = (const float*)d_in[5];
    const float* bv    = (const float*)d_in[6];
    const float* alpha = (const float*)d_in[7];
    float* out = (float*)d_out;

    cudaFuncSetAttribute(attn_kernel, cudaFuncAttributeMaxDynamicSharedMemorySize, SMEM_BYTES);

    proj_kernel<<<dim3(N_ / 32, B_), 256>>>(x, wq, bq, wk, bk, wv, bv);
    attn_kernel<<<dim3(N_ / 64, B_), 256, SMEM_BYTES>>>(x, alpha, out);
}

// round 11
// speedup vs baseline: 5.6601x; 1.1915x over previous
#include <cuda_runtime.h>
#include <cuda_bf16.h>
#include <cuda_fp16.h>
#include <cstdint>

#define B_ 8
#define C_ 256
#define N_ 4096

typedef unsigned int u32;

// ---------------- device scratch (allocation-free rule) ----------------
__device__ __align__(16) __nv_bfloat16 g_qh[B_ * N_ * 32];   // [b][n][d]
__device__ __align__(16) __nv_bfloat16 g_ql[B_ * N_ * 32];
__device__ __align__(16) __nv_bfloat16 g_kh[B_ * N_ * 32];
__device__ __align__(16) __nv_bfloat16 g_kl[B_ * N_ * 32];
__device__ __align__(16) __half       g_v16[(size_t)B_ * C_ * N_];  // [b][c][n] fp16

// ---------------- helpers ----------------
__device__ __forceinline__ u32 smem_u32(const void* p) {
    u32 a;
    asm("{ .reg .u64 t; cvta.to.shared.u64 t, %1; cvt.u32.u64 %0, t; }" : "=r"(a) : "l"(p));
    return a;
}
__device__ __forceinline__ u32 pack_bf2(__nv_bfloat16 a, __nv_bfloat16 b) {
    __nv_bfloat162 t = __halves2bfloat162(a, b);
    return *reinterpret_cast<u32*>(&t);
}
__device__ __forceinline__ void mma_bf16(float* c, const u32* a, const u32* b) {
    asm volatile(
        "mma.sync.aligned.m16n8k16.row.col.f32.bf16.bf16.f32 "
        "{%0,%1,%2,%3}, {%4,%5,%6,%7}, {%8,%9}, {%0,%1,%2,%3};"
        : "+f"(c[0]), "+f"(c[1]), "+f"(c[2]), "+f"(c[3])
        : "r"(a[0]), "r"(a[1]), "r"(a[2]), "r"(a[3]), "r"(b[0]), "r"(b[1]));
}
__device__ __forceinline__ void mma_f16(float* c, const u32* a, const u32* b) {
    asm volatile(
        "mma.sync.aligned.m16n8k16.row.col.f32.f16.f16.f32 "
        "{%0,%1,%2,%3}, {%4,%5,%6,%7}, {%8,%9}, {%0,%1,%2,%3};"
        : "+f"(c[0]), "+f"(c[1]), "+f"(c[2]), "+f"(c[3])
        : "r"(a[0]), "r"(a[1]), "r"(a[2]), "r"(a[3]), "r"(b[0]), "r"(b[1]));
}
__device__ __forceinline__ void ldm4(u32* r, u32 addr) {
    asm volatile("ldmatrix.sync.aligned.m8n8.x4.shared.b16 {%0,%1,%2,%3}, [%4];"
                 : "=r"(r[0]), "=r"(r[1]), "=r"(r[2]), "=r"(r[3]) : "r"(addr));
}
// ldmatrix address: 16-row region at (row0, colh halves), 40-half row stride
__device__ __forceinline__ u32 lma(u32 sbase, u32 region, int row0, int colh, int lane) {
    int lr = lane & 15, lc = (lane >> 4) * 8;
    return sbase + region + (u32)((row0 + lr) * 40 + colh + lc) * 2;
}
// bf16 split (for q/k)
__device__ __forceinline__ void pack_split(float a, float b, u32& h, u32& l) {
    __nv_bfloat16 ha = __float2bfloat16(a), hb = __float2bfloat16(b);
    h = pack_bf2(ha, hb);
    l = pack_bf2(__float2bfloat16(a - __bfloat162float(ha)),
                 __float2bfloat16(b - __bfloat162float(hb)));
}
// cp.async 16B
__device__ __forceinline__ void cp16(u32 dst, const void* src) {
    asm volatile("cp.async.cg.shared.global [%0], [%1], 16;" :: "r"(dst), "l"(src) : "memory");
}
#define CP_COMMIT() asm volatile("cp.async.commit_group;" ::: "memory")
#define CP_WAIT1()  asm volatile("cp.async.wait_group 1;" ::: "memory")
#define CP_WAIT0()  asm volatile("cp.async.wait_group 0;" ::: "memory")

// stage-relative smem offsets; 2 stages of 25600 B
#define O_KH 0u
#define O_KL 2560u
#define O_V  5120u
#define STAGE_BYTES 25600u
#define SMEM_BYTES 51200u

// ---------------- projection kernel (unchanged, passing) ----------------
__device__ __forceinline__ void dot4(const float* __restrict__ xs, int n,
                                     const float* __restrict__ w0, const float* __restrict__ w1,
                                     const float* __restrict__ w2, const float* __restrict__ w3,
                                     float& a0, float& a1, float& a2, float& a3) {
#pragma unroll 8
    for (int c = 0; c < 256; c += 4) {
        float x0 = xs[(c + 0) * 33 + n], x1 = xs[(c + 1) * 33 + n];
        float x2 = xs[(c + 2) * 33 + n], x3 = xs[(c + 3) * 33 + n];
        float4 m;
        m = *(const float4*)(w0 + c); a0 += x0 * m.x + x1 * m.y + x2 * m.z + x3 * m.w;
        m = *(const float4*)(w1 + c); a1 += x0 * m.x + x1 * m.y + x2 * m.z + x3 * m.w;
        m = *(const float4*)(w2 + c); a2 += x0 * m.x + x1 * m.y + x2 * m.z + x3 * m.w;
        m = *(const float4*)(w3 + c); a3 += x0 * m.x + x1 * m.y + x2 * m.z + x3 * m.w;
    }
}

__device__ __forceinline__ void split_store(__nv_bfloat16* hi, __nv_bfloat16* lo,
                                            float a0, float a1, float a2, float a3) {
    u32 h0, l0, h1, l1;
    pack_split(a0, a1, h0, l0);
    pack_split(a2, a3, h1, l1);
    uint2 hv; hv.x = h0; hv.y = h1;
    uint2 lv; lv.x = l0; lv.y = l1;
    *(uint2*)hi = hv; *(uint2*)lo = lv;
}

__global__ __launch_bounds__(256)
void proj_kernel(const float* __restrict__ x,
                 const float* __restrict__ wq, const float* __restrict__ bq,
                 const float* __restrict__ wk, const float* __restrict__ bk,
                 const float* __restrict__ wv, const float* __restrict__ bv) {
    __shared__ float xs[256 * 33];
    const int b = blockIdx.y, n0 = blockIdx.x * 32, t = threadIdx.x;
    const float* xb = x + (size_t)b * C_ * N_;
#pragma unroll
    for (int r = 0; r < 32; r++) {
        int idx = t + r * 256, c = idx >> 5, n = idx & 31;
        xs[c * 33 + n] = xb[(size_t)c * N_ + n0 + n];
    }
    __syncthreads();
    const int n = t & 31, dg = t >> 5, r0 = dg * 4;
    const size_t nbase = (size_t)b * N_ + n0 + n;
    {   // Q
        float a0 = bq[r0], a1 = bq[r0 + 1], a2 = bq[r0 + 2], a3 = bq[r0 + 3];
        dot4(xs, n, wq + (size_t)r0 * 256, wq + (size_t)(r0 + 1) * 256,
             wq + (size_t)(r0 + 2) * 256, wq + (size_t)(r0 + 3) * 256, a0, a1, a2, a3);
        split_store(&g_qh[nbase * 32 + r0], &g_ql[nbase * 32 + r0], a0, a1, a2, a3);
    }
    {   // K
        float a0 = bk[r0], a1 = bk[r0 + 1], a2 = bk[r0 + 2], a3 = bk[r0 + 3];
        dot4(xs, n, wk + (size_t)r0 * 256, wk + (size_t)(r0 + 1) * 256,
             wk + (size_t)(r0 + 2) * 256, wk + (size_t)(r0 + 3) * 256, a0, a1, a2, a3);
        split_store(&g_kh[nbase * 32 + r0], &g_kl[nbase * 32 + r0], a0, a1, a2, a3);
    }
    // V: fp16 transposed [b][c][n]
#pragma unroll
    for (int gg = 0; gg < 8; gg++) {
        int c0 = gg * 32 + r0;
        float a0 = bv[c0], a1 = bv[c0 + 1], a2 = bv[c0 + 2], a3 = bv[c0 + 3];
        dot4(xs, n, wv + (size_t)c0 * 256, wv + (size_t)(c0 + 1) * 256,
             wv + (size_t)(c0 + 2) * 256, wv + (size_t)(c0 + 3) * 256, a0, a1, a2, a3);
        float av[4] = {a0, a1, a2, a3};
#pragma unroll
        for (int e = 0; e < 4; e++) {
            size_t o = ((size_t)(b * C_ + c0 + e) << 12) + n0 + n;
            g_v16[o] = __float2half_rn(av[e]);
        }
    }
}

// ---------------- FA2-style flash attention, cp.async double-buffered ----------------
// CTA: 64 queries; warp group wg=wid>>1 owns rows wg*16..+15, (wid&1) = c half.
// QK: bf16 3-term split. PV: P single fp16 (regs) x V fp16; l summed from rounded P.
__global__ __launch_bounds__(256, 2)
void attn_kernel(const float* __restrict__ x, const float* __restrict__ alphap,
                 float* __restrict__ out) {
    extern __shared__ char smem[];
    const u32 sb = smem_u32(smem);
    const int b = blockIdx.y, i0 = blockIdx.x * 64;
    const int t = threadIdx.x, wid = t >> 5, lane = t & 31;
    const int wg = wid >> 1, r0 = wg * 16;
    const int cw = (wid & 1) * 128;
    const int r = lane >> 2;

    // ---- stage Q (once), load A fragments, free the smem ----
    {
        int row = t >> 2, ck = t & 3;
        size_t g = ((size_t)(b * N_ + i0 + row) << 5) + ck * 8;
        *(uint4*)(smem + O_V + row * 80 + ck * 16) = *(const uint4*)(g_qh + g);
        *(uint4*)(smem + O_V + 5120 + row * 80 + ck * 16) = *(const uint4*)(g_ql + g);
    }
    __syncthreads();
    u32 qh[2][4], ql[2][4];
    ldm4(qh[0], lma(sb, O_V, r0, 0, lane));
    ldm4(qh[1], lma(sb, O_V, r0, 16, lane));
    ldm4(ql[0], lma(sb, O_V + 5120, r0, 0, lane));
    ldm4(ql[1], lma(sb, O_V + 5120, r0, 16, lane));
    __syncthreads();

    float acc[16][4];
#pragma unroll
    for (int nb = 0; nb < 16; nb++)
#pragma unroll
        for (int e = 0; e < 4; e++) acc[nb][e] = 0.f;
    float m0 = -1e30f, m1 = -1e30f, l0 = 0.f, l1 = 0.f;

    // ---- per-thread load slots ----
    const int krow = (t & 127) >> 2, kck = t & 3;
    const __nv_bfloat16* ksrc = (t < 128) ? g_kh : g_kl;
    const u32 kdst_local = ((t < 128) ? O_KH : O_KL) + (u32)krow * 80 + (u32)kck * 16;
    const char* kgsrc = (const char*)ksrc + ((size_t)(b * N_ + krow) << 6) + kck * 16;
    const int vr = t >> 2, vck = t & 3;
    u32 vdst[4];
    const char* vgsrc[4];
#pragma unroll
    for (int rr = 0; rr < 4; rr++) {
        vdst[rr] = O_V + (u32)(rr * 64 + vr) * 80 + (u32)vck * 16;
        vgsrc[rr] = (const char*)(g_v16 + ((size_t)(b * C_ + rr * 64 + vr) << 12) + vck * 8);
    }
    auto issue_tile = [&](u32 stb, int j0) {
        cp16(sb + stb + kdst_local, kgsrc + (size_t)j0 * 64);
#pragma unroll
        for (int rr = 0; rr < 4; rr++)
            cp16(sb + stb + vdst[rr], vgsrc[rr] + (size_t)j0 * 2);
    };

    // ---- pipeline prologue: stage 0 = tile 0 ----
    issue_tile(0u, 0);
    CP_COMMIT();

    for (int jt = 0; jt < 128; jt++) {
        const int j0 = jt * 32;
        const u32 stb = (u32)(jt & 1) * STAGE_BYTES;
        if (jt < 127) {
            issue_tile((u32)((jt + 1) & 1) * STAGE_BYTES, j0 + 32);
            CP_COMMIT();
            CP_WAIT1();
        } else {
            CP_WAIT0();
        }
        __syncthreads();
        const u32 sbs = sb + stb;

        // ---- S = Q.K^T : 16 rows x 32 j per warp, 3-term bf16 split ----
        float sc[4][4];
#pragma unroll
        for (int nb = 0; nb < 4; nb++)
#pragma unroll
            for (int e = 0; e < 4; e++) sc[nb][e] = 0.f;
#pragma unroll
        for (int kb = 0; kb < 2; kb++)
#pragma unroll
            for (int jh = 0; jh < 2; jh++) {
                u32 rh[4], rl[4];
                ldm4(rh, lma(sbs, O_KH, jh * 16, kb * 16, lane));
                ldm4(rl, lma(sbs, O_KL, jh * 16, kb * 16, lane));
                u32 b0[2] = {rh[0], rh[2]}, b1[2] = {rh[1], rh[3]};
                u32 d0[2] = {rl[0], rl[2]}, d1[2] = {rl[1], rl[3]};
                mma_bf16(sc[jh * 2], qh[kb], b0);
                mma_bf16(sc[jh * 2], ql[kb], b0);
                mma_bf16(sc[jh * 2], qh[kb], d0);
                mma_bf16(sc[jh * 2 + 1], qh[kb], b1);
                mma_bf16(sc[jh * 2 + 1], ql[kb], b1);
                mma_bf16(sc[jh * 2 + 1], qh[kb], d1);
            }

        // ---- in-register online softmax (rows r and r+8) ----
        float mr0 = -1e30f, mr1 = -1e30f;
#pragma unroll
        for (int nb = 0; nb < 4; nb++) {
            mr0 = fmaxf(mr0, fmaxf(sc[nb][0], sc[nb][1]));
            mr1 = fmaxf(mr1, fmaxf(sc[nb][2], sc[nb][3]));
        }
        mr0 = fmaxf(mr0, __shfl_xor_sync(0xffffffffu, mr0, 1));
        mr0 = fmaxf(mr0, __shfl_xor_sync(0xffffffffu, mr0, 2));
        mr1 = fmaxf(mr1, __shfl_xor_sync(0xffffffffu, mr1, 1));
        mr1 = fmaxf(mr1, __shfl_xor_sync(0xffffffffu, mr1, 2));
        bool upd = (mr0 > m0) || (mr1 > m1);
        upd = __any_sync(0xffffffffu, upd);
        float mn0 = fmaxf(m0, mr0), mn1 = fmaxf(m1, mr1);
        float al0 = __expf(m0 - mn0), al1 = __expf(m1 - mn1);
        m0 = mn0; m1 = mn1;

        // P: fp16 fragments; l accumulates the ROUNDED p (num/den consistent)
        u32 ph[2][4];
        float ls0 = 0.f, ls1 = 0.f;
#pragma unroll
        for (int nb = 0; nb < 4; nb++) {
            float p0 = __expf(sc[nb][0] - mn0);
            float p1 = __expf(sc[nb][1] - mn0);
            float p2 = __expf(sc[nb][2] - mn1);
            float p3 = __expf(sc[nb][3] - mn1);
            __half2 h01 = __floats2half2_rn(p0, p1);
            __half2 h23 = __floats2half2_rn(p2, p3);
            float2 f01 = __half22float2(h01);
            float2 f23 = __half22float2(h23);
            ls0 += f01.x + f01.y;
            ls1 += f23.x + f23.y;
            ph[nb >> 1][(nb & 1) * 2]     = *reinterpret_cast<u32*>(&h01);
            ph[nb >> 1][(nb & 1) * 2 + 1] = *reinterpret_cast<u32*>(&h23);
        }
        ls0 += __shfl_xor_sync(0xffffffffu, ls0, 1);
        ls0 += __shfl_xor_sync(0xffffffffu, ls0, 2);
        ls1 += __shfl_xor_sync(0xffffffffu, ls1, 1);
        ls1 += __shfl_xor_sync(0xffffffffu, ls1, 2);
        l0 = l0 * al0 + ls0;
        l1 = l1 * al1 + ls1;

        // rescale output accumulators only when a max actually moved
        if (upd) {
#pragma unroll
            for (int nb = 0; nb < 16; nb++) {
                acc[nb][0] *= al0; acc[nb][1] *= al0;
                acc[nb][2] *= al1; acc[nb][3] *= al1;
            }
        }

        // ---- O += P.V : A=P (regs, fp16), B=V fp16 [c][j] (smem) ----
#pragma unroll
        for (int cb = 0; cb < 8; cb++) {
            int crow = cw + cb * 16;
            u32 v0[4], v1[4];
            ldm4(v0, lma(sbs, O_V, crow, 0, lane));
            ldm4(v1, lma(sbs, O_V, crow, 16, lane));
            u32 b00[2] = {v0[0], v0[2]}, b01[2] = {v1[0], v1[2]};
            u32 b10[2] = {v0[1], v0[3]}, b11[2] = {v1[1], v1[3]};
            float* A0 = acc[cb * 2];
            float* A1 = acc[cb * 2 + 1];
            mma_f16(A0, ph[0], b00); mma_f16(A0, ph[1], b01);
            mma_f16(A1, ph[0], b10); mma_f16(A1, ph[1], b11);
        }
        __syncthreads();
    }

    // ---- epilogue: stage O through smem, coalesced [b][c][n] writes ----
    const float alpha0 = alphap[0];
    const float s0 = alpha0 / l0, s1 = alpha0 / l1;
    float* stg = (float*)smem;    // [128 c][68 i-pad] f32
    const int qd = lane & 3;
#pragma unroll 1
    for (int phs = 0; phs < 2; phs++) {
        if ((wid & 1) == phs) {
#pragma unroll
            for (int nb = 0; nb < 16; nb++) {
                int c2 = nb * 8 + 2 * qd;
                int ir = r0 + r;
                stg[c2 * 68 + ir]           = acc[nb][0] * s0;
                stg[(c2 + 1) * 68 + ir]     = acc[nb][1] * s0;
                stg[c2 * 68 + ir + 8]       = acc[nb][2] * s1;
                stg[(c2 + 1) * 68 + ir + 8] = acc[nb][3] * s1;
            }
        }
        __syncthreads();
        int cbase = phs * 128;
#pragma unroll
        for (int pass = 0; pass < 2; pass++) {
            int c = pass * 64 + (t >> 2);
            int i4 = (t & 3) * 16;
            size_t g = ((size_t)(b * C_ + cbase + c) << 12) + i0 + i4;
#pragma unroll
            for (int e = 0; e < 4; e++) {
                float4 xr = *(const float4*)(x + g + e * 4);
                float4 vv = *(const float4*)&stg[c * 68 + i4 + e * 4];
                vv.x += xr.x; vv.y += xr.y; vv.z += xr.z; vv.w += xr.w;
                *(float4*)(out + g + e * 4) = vv;
            }
        }
        __syncthreads();
    }
}

// ---------------- launch ----------------
extern "C" void kernel_launch(void* const* d_in, const int* in_sizes, int n_in,
                              void* d_out, int out_size) {
    const float* x     = (const float*)d_in[0];
    const float* wq    = (const float*)d_in[1];
    const float* bq    = (const float*)d_in[2];
    const float* wk    = (const float*)d_in[3];
    const float* bk    = (const float*)d_in[4];
    const float* wv    = (const float*)d_in[5];
    const float* bv    = (const float*)d_in[6];
    const float* alpha = (const float*)d_in[7];
    float* out = (float*)d_out;

    cudaFuncSetAttribute(attn_kernel, cudaFuncAttributeMaxDynamicSharedMemorySize, SMEM_BYTES);

    proj_kernel<<<dim3(N_ / 32, B_), 256>>>(x, wq, bq, wk, bk, wv, bv);
    attn_kernel<<<dim3(N_ / 64, B_), 256, SMEM_BYTES>>>(x, alpha, out);
}

// round 16
// speedup vs baseline: 8.9247x; 1.5768x over previous
#include <cuda_runtime.h>
#include <cuda_bf16.h>
#include <cuda_fp16.h>
#include <cstdint>

#define B_ 8
#define C_ 256
#define N_ 4096

typedef unsigned int u32;

// ---------------- device scratch (allocation-free rule) ----------------
__device__ __align__(16) __nv_bfloat16 g_qh[B_ * N_ * 32];   // [b][n][d]
__device__ __align__(16) __nv_bfloat16 g_ql[B_ * N_ * 32];
__device__ __align__(16) __nv_bfloat16 g_kh[B_ * N_ * 32];
__device__ __align__(16) __nv_bfloat16 g_kl[B_ * N_ * 32];
__device__ __align__(16) __half       g_v16[(size_t)B_ * C_ * N_];  // [b][c][n] fp16
__device__ __align__(16) __nv_bfloat16 g_xh[(size_t)B_ * C_ * N_];  // [b][c][n]
__device__ __align__(16) __nv_bfloat16 g_xl[(size_t)B_ * C_ * N_];
__device__ __align__(16) __nv_bfloat16 g_wh[320 * 256];             // [o][c] rows: q,k,v
__device__ __align__(16) __nv_bfloat16 g_wl[320 * 256];

// ---------------- helpers ----------------
__device__ __forceinline__ u32 smem_u32(const void* p) {
    u32 a;
    asm("{ .reg .u64 t; cvta.to.shared.u64 t, %1; cvt.u32.u64 %0, t; }" : "=r"(a) : "l"(p));
    return a;
}
__device__ __forceinline__ u32 pack_bf2(__nv_bfloat16 a, __nv_bfloat16 b) {
    __nv_bfloat162 t = __halves2bfloat162(a, b);
    return *reinterpret_cast<u32*>(&t);
}
__device__ __forceinline__ void mma_bf16(float* c, const u32* a, const u32* b) {
    asm volatile(
        "mma.sync.aligned.m16n8k16.row.col.f32.bf16.bf16.f32 "
        "{%0,%1,%2,%3}, {%4,%5,%6,%7}, {%8,%9}, {%0,%1,%2,%3};"
        : "+f"(c[0]), "+f"(c[1]), "+f"(c[2]), "+f"(c[3])
        : "r"(a[0]), "r"(a[1]), "r"(a[2]), "r"(a[3]), "r"(b[0]), "r"(b[1]));
}
__device__ __forceinline__ void mma_f16(float* c, const u32* a, const u32* b) {
    asm volatile(
        "mma.sync.aligned.m16n8k16.row.col.f32.f16.f16.f32 "
        "{%0,%1,%2,%3}, {%4,%5,%6,%7}, {%8,%9}, {%0,%1,%2,%3};"
        : "+f"(c[0]), "+f"(c[1]), "+f"(c[2]), "+f"(c[3])
        : "r"(a[0]), "r"(a[1]), "r"(a[2]), "r"(a[3]), "r"(b[0]), "r"(b[1]));
}
__device__ __forceinline__ void ldm4(u32* r, u32 addr) {
    asm volatile("ldmatrix.sync.aligned.m8n8.x4.shared.b16 {%0,%1,%2,%3}, [%4];"
                 : "=r"(r[0]), "=r"(r[1]), "=r"(r[2]), "=r"(r[3]) : "r"(addr));
}
__device__ __forceinline__ void ldm4t(u32* r, u32 addr) {
    asm volatile("ldmatrix.sync.aligned.m8n8.x4.trans.shared.b16 {%0,%1,%2,%3}, [%4];"
                 : "=r"(r[0]), "=r"(r[1]), "=r"(r[2]), "=r"(r[3]) : "r"(addr));
}
// ldmatrix address: 16-row region at (row0, colh halves), 40-half row stride
__device__ __forceinline__ u32 lma(u32 sbase, u32 region, int row0, int colh, int lane) {
    int lr = lane & 15, lc = (lane >> 4) * 8;
    return sbase + region + (u32)((row0 + lr) * 40 + colh + lc) * 2;
}
// bf16 split
__device__ __forceinline__ void pack_split(float a, float b, u32& h, u32& l) {
    __nv_bfloat16 ha = __float2bfloat16(a), hb = __float2bfloat16(b);
    h = pack_bf2(ha, hb);
    l = pack_bf2(__float2bfloat16(a - __bfloat162float(ha)),
                 __float2bfloat16(b - __bfloat162float(hb)));
}
// cp.async 16B
__device__ __forceinline__ void cp16(u32 dst, const void* src) {
    asm volatile("cp.async.cg.shared.global [%0], [%1], 16;" :: "r"(dst), "l"(src) : "memory");
}
#define CP_COMMIT() asm volatile("cp.async.commit_group;" ::: "memory")
#define CP_WAIT1()  asm volatile("cp.async.wait_group 1;" ::: "memory")
#define CP_WAIT0()  asm volatile("cp.async.wait_group 0;" ::: "memory")

// attn smem: stage-relative offsets; 2 stages of 25600 B
#define O_KH 0u
#define O_KL 2560u
#define O_V  5120u
#define STAGE_BYTES 25600u
#define SMEM_BYTES 51200u

// proj smem: A [64 c][272B rows] h/l, B [64 o][144B rows] h/l
#define PA_H 0u
#define PA_L 17408u
#define PB_H 34816u
#define PB_L 44032u
#define PSTAGE 53248u
#define PSMEM 106496u

// ---------------- prep: weight split [320][256] ----------------
__global__ __launch_bounds__(256)
void wsplit_kernel(const float* __restrict__ wq, const float* __restrict__ wk,
                   const float* __restrict__ wv) {
    int e = blockIdx.x * 1024 + threadIdx.x * 4;
    int o = e >> 8, c = e & 255;
    const float* src = (o < 32) ? wq + o * 256
                     : (o < 64) ? wk + (o - 32) * 256
                                : wv + (o - 64) * 256;
    float4 v = *(const float4*)(src + c);
    u32 h0, l0, h1, l1;
    pack_split(v.x, v.y, h0, l0);
    pack_split(v.z, v.w, h1, l1);
    uint2 hv; hv.x = h0; hv.y = h1;
    uint2 lv; lv.x = l0; lv.y = l1;
    *(uint2*)(g_wh + e) = hv;
    *(uint2*)(g_wl + e) = lv;
}

// ---------------- prep: x split (elementwise, layout preserved) ----------------
__global__ __launch_bounds__(256)
void xsplit_kernel(const float* __restrict__ x) {
    size_t e = ((size_t)blockIdx.x * 256 + threadIdx.x) * 4;
    float4 v = *(const float4*)(x + e);
    u32 h0, l0, h1, l1;
    pack_split(v.x, v.y, h0, l0);
    pack_split(v.z, v.w, h1, l1);
    uint2 hv; hv.x = h0; hv.y = h1;
    uint2 lv; lv.x = l0; lv.y = l1;
    *(uint2*)(g_xh + e) = hv;
    *(uint2*)(g_xl + e) = lv;
}

// ---------------- projections as bf16-split HMMA GEMM ----------------
// grid (32 pixel-tiles, 5 o-tiles, 8 b). CTA: 128 pix x 64 out, k=256 in 4 chunks.
// o-tile 0 = [q(32); k(32)] -> g_qh/ql/kh/kl [b][n][32]; tiles 1-4 = v -> g_v16 [b][c][n].
__global__ __launch_bounds__(256, 2)
void proj_mma_kernel(const float* __restrict__ bq, const float* __restrict__ bk,
                     const float* __restrict__ bv) {
    extern __shared__ char smem[];
    const u32 sb = smem_u32(smem);
    const int b = blockIdx.z, ot = blockIdx.y, n0 = blockIdx.x * 128;
    const int t = threadIdx.x, wid = t >> 5, lane = t & 31;
    const int mw = wid >> 1, nw = wid & 1;   // 4 m-warps x 2 n-warps
    const int o0 = ot * 64;

    auto issue = [&](int kk) {
        u32 st = sb + (u32)(kk & 1) * PSTAGE;
        int c0 = kk * 64;
#pragma unroll
        for (int i = 0; i < 4; i++) {
            int idx = t + i * 256, row = idx >> 4, ch = idx & 15;
            size_t gsrc = ((size_t)(b * C_ + c0 + row) << 12) + n0 + ch * 8;
            cp16(st + PA_H + (u32)(row * 272 + ch * 16), g_xh + gsrc);
            cp16(st + PA_L + (u32)(row * 272 + ch * 16), g_xl + gsrc);
        }
#pragma unroll
        for (int i = 0; i < 2; i++) {
            int idx = t + i * 256, row = idx >> 3, ch = idx & 7;
            cp16(st + PB_H + (u32)(row * 144 + ch * 16), g_wh + (o0 + row) * 256 + c0 + ch * 8);
            cp16(st + PB_L + (u32)(row * 144 + ch * 16), g_wl + (o0 + row) * 256 + c0 + ch * 8);
        }
        CP_COMMIT();
    };

    float acc[2][4][4];
#pragma unroll
    for (int mi = 0; mi < 2; mi++)
#pragma unroll
        for (int ni = 0; ni < 4; ni++)
#pragma unroll
            for (int e = 0; e < 4; e++) acc[mi][ni][e] = 0.f;

    issue(0);
    for (int kk = 0; kk < 4; kk++) {
        CP_WAIT0();
        __syncthreads();
        if (kk < 3) issue(kk + 1);
        const u32 st = sb + (u32)(kk & 1) * PSTAGE;
#pragma unroll
        for (int ks = 0; ks < 4; ks++) {
            u32 ah[2][4], al[2][4];
#pragma unroll
            for (int mi = 0; mi < 2; mi++) {
                int p0w = mw * 32 + mi * 16;
                int row = ks * 16 + (lane & 7) + ((lane & 16) ? 8 : 0);
                int colh = p0w + ((lane & 8) ? 8 : 0);
                ldm4t(ah[mi], st + PA_H + (u32)(row * 272 + colh * 2));
                ldm4t(al[mi], st + PA_L + (u32)(row * 272 + colh * 2));
            }
#pragma unroll
            for (int bi = 0; bi < 2; bi++) {
                int row0 = nw * 32 + bi * 16;
                int lr = lane & 15, lc = (lane >> 4) * 8;
                u32 ba = (u32)((row0 + lr) * 144 + (ks * 16 + lc) * 2);
                u32 bh[4], bl[4];
                ldm4(bh, st + PB_H + ba);
                ldm4(bl, st + PB_L + ba);
#pragma unroll
                for (int sub = 0; sub < 2; sub++) {
                    int ni = bi * 2 + sub;
                    u32 bfh[2] = {bh[sub], bh[sub + 2]};
                    u32 bfl[2] = {bl[sub], bl[sub + 2]};
#pragma unroll
                    for (int mi = 0; mi < 2; mi++) {
                        mma_bf16(acc[mi][ni], ah[mi], bfh);
                        mma_bf16(acc[mi][ni], al[mi], bfh);
                        mma_bf16(acc[mi][ni], ah[mi], bfl);
                    }
                }
            }
        }
    }

    if (ot == 0) {
        // q/k epilogue: split-store directly from fragments
#pragma unroll
        for (int mi = 0; mi < 2; mi++)
#pragma unroll
            for (int ni = 0; ni < 4; ni++) {
                int o = nw * 32 + ni * 8 + (lane & 3) * 2;
                int pixl = mw * 32 + mi * 16 + (lane >> 2);
                bool isq = o < 32;
                int d = isq ? o : o - 32;
                float b0 = isq ? bq[o] : bk[o - 32];
                float b1 = isq ? bq[o + 1] : bk[o - 31];
#pragma unroll
                for (int half = 0; half < 2; half++) {
                    int pix = n0 + pixl + half * 8;
                    float e0 = acc[mi][ni][half * 2 + 0] + b0;
                    float e1 = acc[mi][ni][half * 2 + 1] + b1;
                    u32 h, l;
                    pack_split(e0, e1, h, l);
                    size_t base = ((size_t)(b * N_ + pix) << 5) + d;
                    if (isq) { *(u32*)(g_qh + base) = h; *(u32*)(g_ql + base) = l; }
                    else     { *(u32*)(g_kh + base) = h; *(u32*)(g_kl + base) = l; }
                }
            }
    } else {
        // v epilogue: stage [64 o][128 pix] fp16 in smem, coalesced row copy
        const int vbase = o0 - 64;
        __syncthreads();
#pragma unroll
        for (int mi = 0; mi < 2; mi++)
#pragma unroll
            for (int ni = 0; ni < 4; ni++) {
                int o = nw * 32 + ni * 8 + (lane & 3) * 2;
                float b0 = bv[vbase + o], b1 = bv[vbase + o + 1];
                int pixl = mw * 32 + mi * 16 + (lane >> 2);
#pragma unroll
                for (int half = 0; half < 2; half++) {
                    int pl = pixl + half * 8;
                    *(__half*)(smem + o * 272 + pl * 2) =
                        __float2half_rn(acc[mi][ni][half * 2 + 0] + b0);
                    *(__half*)(smem + (o + 1) * 272 + pl * 2) =
                        __float2half_rn(acc[mi][ni][half * 2 + 1] + b1);
                }
            }
        __syncthreads();
#pragma unroll
        for (int i = 0; i < 4; i++) {
            int idx = t + i * 256, row = idx >> 4, ch = idx & 15;
            uint4 v = *(uint4*)(smem + row * 272 + ch * 16);
            *(uint4*)(g_v16 + ((size_t)(b * C_ + vbase + row) << 12) + n0 + ch * 8) = v;
        }
    }
}

// ---------------- FA2-style flash attention (unchanged from R10, proven) ----------------
__global__ __launch_bounds__(256, 2)
void attn_kernel(const float* __restrict__ x, const float* __restrict__ alphap,
                 float* __restrict__ out) {
    extern __shared__ char smem[];
    const u32 sb = smem_u32(smem);
    const int b = blockIdx.y, i0 = blockIdx.x * 64;
    const int t = threadIdx.x, wid = t >> 5, lane = t & 31;
    const int wg = wid >> 1, r0 = wg * 16;
    const int cw = (wid & 1) * 128;
    const int r = lane >> 2;

    {
        int row = t >> 2, ck = t & 3;
        size_t g = ((size_t)(b * N_ + i0 + row) << 5) + ck * 8;
        *(uint4*)(smem + O_V + row * 80 + ck * 16) = *(const uint4*)(g_qh + g);
        *(uint4*)(smem + O_V + 5120 + row * 80 + ck * 16) = *(const uint4*)(g_ql + g);
    }
    __syncthreads();
    u32 qh[2][4], ql[2][4];
    ldm4(qh[0], lma(sb, O_V, r0, 0, lane));
    ldm4(qh[1], lma(sb, O_V, r0, 16, lane));
    ldm4(ql[0], lma(sb, O_V + 5120, r0, 0, lane));
    ldm4(ql[1], lma(sb, O_V + 5120, r0, 16, lane));
    __syncthreads();

    float acc[16][4];
#pragma unroll
    for (int nb = 0; nb < 16; nb++)
#pragma unroll
        for (int e = 0; e < 4; e++) acc[nb][e] = 0.f;
    float m0 = -1e30f, m1 = -1e30f, l0 = 0.f, l1 = 0.f;

    const int krow = (t & 127) >> 2, kck = t & 3;
    const __nv_bfloat16* ksrc = (t < 128) ? g_kh : g_kl;
    const u32 kdst_local = ((t < 128) ? O_KH : O_KL) + (u32)krow * 80 + (u32)kck * 16;
    const char* kgsrc = (const char*)ksrc + ((size_t)(b * N_ + krow) << 6) + kck * 16;
    const int vr = t >> 2, vck = t & 3;
    u32 vdst[4];
    const char* vgsrc[4];
#pragma unroll
    for (int rr = 0; rr < 4; rr++) {
        vdst[rr] = O_V + (u32)(rr * 64 + vr) * 80 + (u32)vck * 16;
        vgsrc[rr] = (const char*)(g_v16 + ((size_t)(b * C_ + rr * 64 + vr) << 12) + vck * 8);
    }
    auto issue_tile = [&](u32 stb, int j0) {
        cp16(sb + stb + kdst_local, kgsrc + (size_t)j0 * 64);
#pragma unroll
        for (int rr = 0; rr < 4; rr++)
            cp16(sb + stb + vdst[rr], vgsrc[rr] + (size_t)j0 * 2);
    };

    issue_tile(0u, 0);
    CP_COMMIT();

    for (int jt = 0; jt < 128; jt++) {
        const int j0 = jt * 32;
        const u32 stb = (u32)(jt & 1) * STAGE_BYTES;
        if (jt < 127) {
            issue_tile((u32)((jt + 1) & 1) * STAGE_BYTES, j0 + 32);
            CP_COMMIT();
            CP_WAIT1();
        } else {
            CP_WAIT0();
        }
        __syncthreads();
        const u32 sbs = sb + stb;

        float sc[4][4];
#pragma unroll
        for (int nb = 0; nb < 4; nb++)
#pragma unroll
            for (int e = 0; e < 4; e++) sc[nb][e] = 0.f;
#pragma unroll
        for (int kb = 0; kb < 2; kb++)
#pragma unroll
            for (int jh = 0; jh < 2; jh++) {
                u32 rh[4], rl[4];
                ldm4(rh, lma(sbs, O_KH, jh * 16, kb * 16, lane));
                ldm4(rl, lma(sbs, O_KL, jh * 16, kb * 16, lane));
                u32 b0[2] = {rh[0], rh[2]}, b1[2] = {rh[1], rh[3]};
                u32 d0[2] = {rl[0], rl[2]}, d1[2] = {rl[1], rl[3]};
                mma_bf16(sc[jh * 2], qh[kb], b0);
                mma_bf16(sc[jh * 2], ql[kb], b0);
                mma_bf16(sc[jh * 2], qh[kb], d0);
                mma_bf16(sc[jh * 2 + 1], qh[kb], b1);
                mma_bf16(sc[jh * 2 + 1], ql[kb], b1);
                mma_bf16(sc[jh * 2 + 1], qh[kb], d1);
            }

        float mr0 = -1e30f, mr1 = -1e30f;
#pragma unroll
        for (int nb = 0; nb < 4; nb++) {
            mr0 = fmaxf(mr0, fmaxf(sc[nb][0], sc[nb][1]));
            mr1 = fmaxf(mr1, fmaxf(sc[nb][2], sc[nb][3]));
        }
        mr0 = fmaxf(mr0, __shfl_xor_sync(0xffffffffu, mr0, 1));
        mr0 = fmaxf(mr0, __shfl_xor_sync(0xffffffffu, mr0, 2));
        mr1 = fmaxf(mr1, __shfl_xor_sync(0xffffffffu, mr1, 1));
        mr1 = fmaxf(mr1, __shfl_xor_sync(0xffffffffu, mr1, 2));
        bool upd = (mr0 > m0) || (mr1 > m1);
        upd = __any_sync(0xffffffffu, upd);
        float mn0 = fmaxf(m0, mr0), mn1 = fmaxf(m1, mr1);
        float al0 = __expf(m0 - mn0), al1 = __expf(m1 - mn1);
        m0 = mn0; m1 = mn1;

        u32 ph[2][4];
        float ls0 = 0.f, ls1 = 0.f;
#pragma unroll
        for (int nb = 0; nb < 4; nb++) {
            float p0 = __expf(sc[nb][0] - mn0);
            float p1 = __expf(sc[nb][1] - mn0);
            float p2 = __expf(sc[nb][2] - mn1);
            float p3 = __expf(sc[nb][3] - mn1);
            __half2 h01 = __floats2half2_rn(p0, p1);
            __half2 h23 = __floats2half2_rn(p2, p3);
            float2 f01 = __half22float2(h01);
            float2 f23 = __half22float2(h23);
            ls0 += f01.x + f01.y;
            ls1 += f23.x + f23.y;
            ph[nb >> 1][(nb & 1) * 2]     = *reinterpret_cast<u32*>(&h01);
            ph[nb >> 1][(nb & 1) * 2 + 1] = *reinterpret_cast<u32*>(&h23);
        }
        ls0 += __shfl_xor_sync(0xffffffffu, ls0, 1);
        ls0 += __shfl_xor_sync(0xffffffffu, ls0, 2);
        ls1 += __shfl_xor_sync(0xffffffffu, ls1, 1);
        ls1 += __shfl_xor_sync(0xffffffffu, ls1, 2);
        l0 = l0 * al0 + ls0;
        l1 = l1 * al1 + ls1;

        if (upd) {
#pragma unroll
            for (int nb = 0; nb < 16; nb++) {
                acc[nb][0] *= al0; acc[nb][1] *= al0;
                acc[nb][2] *= al1; acc[nb][3] *= al1;
            }
        }

#pragma unroll
        for (int cb = 0; cb < 8; cb++) {
            int crow = cw + cb * 16;
            u32 v0[4], v1[4];
            ldm4(v0, lma(sbs, O_V, crow, 0, lane));
            ldm4(v1, lma(sbs, O_V, crow, 16, lane));
            u32 b00[2] = {v0[0], v0[2]}, b01[2] = {v1[0], v1[2]};
            u32 b10[2] = {v0[1], v0[3]}, b11[2] = {v1[1], v1[3]};
            float* A0 = acc[cb * 2];
            float* A1 = acc[cb * 2 + 1];
            mma_f16(A0, ph[0], b00); mma_f16(A0, ph[1], b01);
            mma_f16(A1, ph[0], b10); mma_f16(A1, ph[1], b11);
        }
        __syncthreads();
    }

    const float alpha0 = alphap[0];
    const float s0 = alpha0 / l0, s1 = alpha0 / l1;
    float* stg = (float*)smem;
    const int qd = lane & 3;
#pragma unroll 1
    for (int phs = 0; phs < 2; phs++) {
        if ((wid & 1) == phs) {
#pragma unroll
            for (int nb = 0; nb < 16; nb++) {
                int c2 = nb * 8 + 2 * qd;
                int ir = r0 + r;
                stg[c2 * 68 + ir]           = acc[nb][0] * s0;
                stg[(c2 + 1) * 68 + ir]     = acc[nb][1] * s0;
                stg[c2 * 68 + ir + 8]       = acc[nb][2] * s1;
                stg[(c2 + 1) * 68 + ir + 8] = acc[nb][3] * s1;
            }
        }
        __syncthreads();
        int cbase = phs * 128;
#pragma unroll
        for (int pass = 0; pass < 2; pass++) {
            int c = pass * 64 + (t >> 2);
            int i4 = (t & 3) * 16;
            size_t g = ((size_t)(b * C_ + cbase + c) << 12) + i0 + i4;
#pragma unroll
            for (int e = 0; e < 4; e++) {
                float4 xr = *(const float4*)(x + g + e * 4);
                float4 vv = *(const float4*)&stg[c * 68 + i4 + e * 4];
                vv.x += xr.x; vv.y += xr.y; vv.z += xr.z; vv.w += xr.w;
                *(float4*)(out + g + e * 4) = vv;
            }
        }
        __syncthreads();
    }
}

// ---------------- launch ----------------
extern "C" void kernel_launch(void* const* d_in, const int* in_sizes, int n_in,
                              void* d_out, int out_size) {
    const float* x     = (const float*)d_in[0];
    const float* wq    = (const float*)d_in[1];
    const float* bq    = (const float*)d_in[2];
    const float* wk    = (const float*)d_in[3];
    const float* bk    = (const float*)d_in[4];
    const float* wv    = (const float*)d_in[5];
    const float* bv    = (const float*)d_in[6];
    const float* alpha = (const float*)d_in[7];
    float* out = (float*)d_out;

    cudaFuncSetAttribute(attn_kernel, cudaFuncAttributeMaxDynamicSharedMemorySize, SMEM_BYTES);
    cudaFuncSetAttribute(proj_mma_kernel, cudaFuncAttributeMaxDynamicSharedMemorySize, PSMEM);

    wsplit_kernel<<<80, 256>>>(wq, wk, wv);
    xsplit_kernel<<<8192, 256>>>(x);
    proj_mma_kernel<<<dim3(32, 5, B_), 256, PSMEM>>>(bq, bk, bv);
    attn_kernel<<<dim3(N_ / 64, B_), 256, SMEM_BYTES>>>(x, alpha, out);
}